// round 1
// baseline (speedup 1.0000x reference)
#include <cuda_runtime.h>
#include <cuda_bf16.h>
#include <math.h>

// ---------------------------------------------------------------------------
// Problem constants
// ---------------------------------------------------------------------------
#define T_   2048
#define H_   1024
#define NH_  16
#define NKV_ 4
#define HD_  64
#define E_   32
#define TOPK_ 4
#define NG_  4
#define TG_  2
#define IM_  384
#define ISH_ 384
#define ROT_ 32      // HD/2
#define EPS_ 1e-5f

// ---------------------------------------------------------------------------
// Scratch (device globals — allocation-free per harness rules)
// ---------------------------------------------------------------------------
__device__ float g_r1     [T_*H_];
__device__ float g_ln1    [T_*H_];
__device__ float g_qkv    [T_*1536];
__device__ float g_q      [T_*NH_*HD_];
__device__ float g_k      [T_*NKV_*HD_];
__device__ float g_v      [T_*NKV_*HD_];
__device__ float g_att    [T_*H_];
__device__ float g_h2     [T_*H_];
__device__ float g_w      [T_*TOPK_];
__device__ int   g_ids    [T_*TOPK_];
__device__ int   g_sorted [T_*TOPK_];
__device__ int   g_slotpos[T_*TOPK_];
__device__ int   g_offs   [E_+1];
__device__ float g_gu     [T_*TOPK_*2*IM_];
__device__ float g_actbuf [T_*TOPK_*IM_];
__device__ float g_slot   [T_*TOPK_*H_];
__device__ float g_gus    [T_*2*ISH_];
__device__ float g_actsh  [T_*ISH_];
__device__ float g_shared [T_*H_];

// ---------------------------------------------------------------------------
// add + RMSNorm (row per block, 256 threads, float4). b / resid optional.
// ---------------------------------------------------------------------------
__global__ __launch_bounds__(256) void add_rms_kernel(
    const float* __restrict__ a, const float* __restrict__ b,
    const float* __restrict__ w, float* __restrict__ resid,
    float* __restrict__ out)
{
    int t = blockIdx.x;
    int i = threadIdx.x;
    float4 va = ((const float4*)(a + (long long)t*H_))[i];
    if (b) {
        float4 vb = ((const float4*)(b + (long long)t*H_))[i];
        va.x += vb.x; va.y += vb.y; va.z += vb.z; va.w += vb.w;
    }
    if (resid) ((float4*)(resid + (long long)t*H_))[i] = va;
    float ss = va.x*va.x + va.y*va.y + va.z*va.z + va.w*va.w;
    __shared__ float sred[8];
    #pragma unroll
    for (int off = 16; off; off >>= 1) ss += __shfl_xor_sync(0xffffffffu, ss, off);
    if ((i & 31) == 0) sred[i >> 5] = ss;
    __syncthreads();
    if (i < 8) {
        float v = sred[i];
        #pragma unroll
        for (int off = 4; off; off >>= 1) v += __shfl_xor_sync(0xffu, v, off);
        if (i == 0) sred[0] = v;
    }
    __syncthreads();
    float rs = rsqrtf(sred[0] / (float)H_ + EPS_);
    float4 vw = ((const float4*)w)[i];
    va.x *= rs * vw.x; va.y *= rs * vw.y; va.z *= rs * vw.z; va.w *= rs * vw.w;
    ((float4*)(out + (long long)t*H_))[i] = va;
}

// ---------------------------------------------------------------------------
// Generic 128x128x8 SGEMM, 256 threads, 8x8 microtile.
//   SEG:    grid.z = expert; rows in [segoffs[z], segoffs[z+1]); B += z*bStride
//   GATHER: A row index taken from gather[globalRow]
//   ADD:    C = A@B + addsrc
// N and K must be multiples of 128 / 8 (all call sites satisfy this).
// ---------------------------------------------------------------------------
template<bool SEG, bool GATHER, bool ADD>
__global__ __launch_bounds__(256) void sgemm_kernel(
    const float* __restrict__ A, const float* __restrict__ Bbase,
    float* __restrict__ C, const float* __restrict__ addsrc,
    int M, int N, int K,
    const int* __restrict__ gather, const int* __restrict__ segoffs,
    long long bStride)
{
    constexpr int BM = 128, BN = 128, BK = 8, TM = 8, TN = 8;
    __shared__ float As[BK][BM];
    __shared__ float Bs[BK][BN];

    int rowBeg, rowEnd;
    int z = 0;
    if (SEG) {
        z = blockIdx.z;
        rowBeg = segoffs[z];
        rowEnd = segoffs[z+1];
    } else {
        rowBeg = 0;
        rowEnd = M;
    }
    int row0 = rowBeg + blockIdx.y * BM;
    if (row0 >= rowEnd) return;
    int col0 = blockIdx.x * BN;

    const float* B = SEG ? (Bbase + (long long)z * bStride) : Bbase;

    int tid  = threadIdx.x;
    int aRow = tid >> 1;           // 0..127
    int aCol = (tid & 1) * 4;      // 0 or 4
    int bRow = tid >> 5;           // 0..7
    int bCol = (tid & 31) * 4;     // 0..124
    int ty   = tid >> 4;           // 0..15
    int tx   = tid & 15;           // 0..15

    int gRow = row0 + aRow;
    bool aValid = gRow < rowEnd;
    int srcRow;
    if (GATHER) srcRow = aValid ? gather[gRow] : 0;
    else        srcRow = aValid ? gRow : 0;
    const float* Aptr = A + (long long)srcRow * K;

    float acc[TM][TN];
    #pragma unroll
    for (int i = 0; i < TM; i++)
        #pragma unroll
        for (int j = 0; j < TN; j++) acc[i][j] = 0.f;

    float regM[TM], regN[TN];

    for (int k0 = 0; k0 < K; k0 += BK) {
        float4 av = make_float4(0.f, 0.f, 0.f, 0.f);
        if (aValid) av = *reinterpret_cast<const float4*>(Aptr + k0 + aCol);
        As[aCol+0][aRow] = av.x;
        As[aCol+1][aRow] = av.y;
        As[aCol+2][aRow] = av.z;
        As[aCol+3][aRow] = av.w;
        float4 bv = *reinterpret_cast<const float4*>(
            B + (long long)(k0 + bRow) * N + col0 + bCol);
        *reinterpret_cast<float4*>(&Bs[bRow][bCol]) = bv;
        __syncthreads();
        #pragma unroll
        for (int k = 0; k < BK; k++) {
            #pragma unroll
            for (int i = 0; i < TM; i++) regM[i] = As[k][ty*TM + i];
            #pragma unroll
            for (int j = 0; j < TN; j++) regN[j] = Bs[k][tx*TN + j];
            #pragma unroll
            for (int i = 0; i < TM; i++)
                #pragma unroll
                for (int j = 0; j < TN; j++)
                    acc[i][j] += regM[i] * regN[j];
        }
        __syncthreads();
    }

    #pragma unroll
    for (int i = 0; i < TM; i++) {
        int r = row0 + ty*TM + i;
        if (r >= rowEnd) break;
        float* Crow = C + (long long)r * N + col0 + tx*TN;
        #pragma unroll
        for (int j = 0; j < TN; j += 4) {
            float4 v = make_float4(acc[i][j], acc[i][j+1], acc[i][j+2], acc[i][j+3]);
            if (ADD) {
                float4 a4 = *reinterpret_cast<const float4*>(
                    addsrc + (long long)r * N + col0 + tx*TN + j);
                v.x += a4.x; v.y += a4.y; v.z += a4.z; v.w += a4.w;
            }
            *reinterpret_cast<float4*>(Crow + j) = v;
        }
    }
}

// ---------------------------------------------------------------------------
// Per-head RMSNorm + RoPE for q and k; copy v. Block = 1 token, 256 threads.
// ---------------------------------------------------------------------------
__global__ __launch_bounds__(256) void qknorm_rope_kernel(
    const float* __restrict__ qkv,
    const float* __restrict__ qw, const float* __restrict__ kw,
    const int* __restrict__ positions,
    float* __restrict__ Qo, float* __restrict__ Ko, float* __restrict__ Vo)
{
    int t = blockIdx.x;
    int warp = threadIdx.x >> 5, lane = threadIdx.x & 31;
    float p = (float)positions[t];

    for (int vec = warp; vec < NH_ + NKV_; vec += 8) {
        bool isq = vec < NH_;
        const float* src = qkv + (long long)t*1536 + vec*HD_;
        float x0 = src[lane], x1 = src[lane + 32];
        float ss = x0*x0 + x1*x1;
        #pragma unroll
        for (int off = 16; off; off >>= 1) ss += __shfl_xor_sync(0xffffffffu, ss, off);
        float r = rsqrtf(ss / (float)HD_ + EPS_);
        const float* w = isq ? qw : kw;
        x0 = x0 * r * w[lane];
        x1 = x1 * r * w[lane + 32];
        // RoPE on dims [0,32): pairs (i, i+16)
        int i = lane & 15;
        float inv = powf(10000.f, -((float)(2*i) / (float)ROT_));
        float ang = p * inv;
        float c = cosf(ang), s = sinf(ang);
        float partner = __shfl_xor_sync(0xffffffffu, x0, 16);
        float y0;
        if (lane < 16) y0 = x0 * c - partner * s;   // x1*c - x2*s
        else           y0 = partner * s + x0 * c;   // x1*s + x2*c
        x0 = y0;
        float* dst = isq ? (Qo + ((long long)t*NH_ + vec)*HD_)
                         : (Ko + ((long long)t*NKV_ + (vec - NH_))*HD_);
        dst[lane] = x0;
        dst[lane + 32] = x1;
    }
    // copy v (256 floats)
    for (int i = threadIdx.x; i < NKV_*HD_; i += blockDim.x)
        Vo[(long long)t*NKV_*HD_ + i] = qkv[(long long)t*1536 + 1280 + i];
}

// ---------------------------------------------------------------------------
// Causal attention, online softmax. 1 thread = 1 query row.
// grid = (T/128, NH), block = 128. K/V tiles (64 keys) in smem, broadcast reads.
// ---------------------------------------------------------------------------
__global__ __launch_bounds__(128) void attn_kernel(
    const float* __restrict__ Q, const float* __restrict__ Kc,
    const float* __restrict__ Vc, float* __restrict__ O)
{
    const int h = blockIdx.y;
    const int kvh = h >> 2;                 // NH/NKV = 4
    const int t = blockIdx.x * 128 + threadIdx.x;
    __shared__ float Ks[64][64];
    __shared__ float Vs[64][64];

    float q[HD_];
    #pragma unroll
    for (int d = 0; d < HD_; d++) q[d] = Q[((long long)t*NH_ + h)*HD_ + d];
    float o[HD_];
    #pragma unroll
    for (int d = 0; d < HD_; d++) o[d] = 0.f;
    float m = -1e30f, l = 0.f;

    int lastS = blockIdx.x * 128 + 127;
    int nTiles = lastS / 64 + 1;
    for (int jt = 0; jt < nTiles; jt++) {
        int s0 = jt * 64;
        for (int idx = threadIdx.x; idx < 64*16; idx += 128) {
            int r = idx >> 4;
            int c = (idx & 15) * 4;
            *(float4*)&Ks[r][c] = *(const float4*)&Kc[((long long)(s0+r)*NKV_ + kvh)*HD_ + c];
            *(float4*)&Vs[r][c] = *(const float4*)&Vc[((long long)(s0+r)*NKV_ + kvh)*HD_ + c];
        }
        __syncthreads();
        int smax = t - s0 + 1;
        if (smax > 64) smax = 64;
        for (int s = 0; s < smax; s++) {
            float dot = 0.f;
            #pragma unroll
            for (int d = 0; d < HD_; d++) dot += q[d] * Ks[s][d];
            float sc = dot * 0.125f;                  // HD^-0.5
            float mn = fmaxf(m, sc);
            float corr = __expf(m - mn);
            float pp = __expf(sc - mn);
            l = l * corr + pp;
            #pragma unroll
            for (int d = 0; d < HD_; d++) o[d] = o[d] * corr + pp * Vs[s][d];
            m = mn;
        }
        __syncthreads();
    }
    float invl = 1.f / l;
    #pragma unroll
    for (int d = 0; d < HD_; d++)
        O[(long long)t*H_ + h*HD_ + d] = o[d] * invl;
}

// ---------------------------------------------------------------------------
// Router: warp per token. Exact replication of group top-k routing (fp32).
// ---------------------------------------------------------------------------
__global__ __launch_bounds__(128) void router_kernel(
    const float* __restrict__ h2, const float* __restrict__ Wg,
    const float* __restrict__ bias, int* __restrict__ ids,
    float* __restrict__ wout)
{
    int warp = threadIdx.x >> 5, lane = threadIdx.x & 31;
    int t = blockIdx.x * 4 + warp;
    const float* h = h2 + (long long)t * H_;
    float acc = 0.f;
    for (int k = 0; k < H_; k++) acc += __ldg(&h[k]) * __ldg(&Wg[k*E_ + lane]);
    float scr = 1.f / (1.f + expf(-acc));
    __shared__ float s_scr[4][E_];
    __shared__ float s_sfc[4][E_];
    s_scr[warp][lane] = scr;
    s_sfc[warp][lane] = scr + bias[lane];
    __syncwarp();
    if (lane == 0) {
        float* sc = s_scr[warp];
        float* sf = s_sfc[warp];
        float gs[NG_];
        for (int g = 0; g < NG_; g++) {
            float m1 = -1e30f, m2 = -1e30f;
            for (int j = 0; j < E_/NG_; j++) {
                float v = sf[g*(E_/NG_) + j];
                if (v > m1) { m2 = m1; m1 = v; }
                else if (v > m2) { m2 = v; }
            }
            gs[g] = m1 + m2;
        }
        int g1 = 0;
        for (int g = 1; g < NG_; g++) if (gs[g] > gs[g1]) g1 = g;
        int g2 = -1;
        for (int g = 0; g < NG_; g++) {
            if (g == g1) continue;
            if (g2 < 0 || gs[g] > gs[g2]) g2 = g;
        }
        bool used[E_];
        for (int e = 0; e < E_; e++) used[e] = false;
        int sel[TOPK_];
        for (int kk = 0; kk < TOPK_; kk++) {
            int best = -1; float bv = -1e30f;
            for (int e = 0; e < E_; e++) {
                int g = e >> 3;
                if ((g != g1 && g != g2) || used[e]) continue;
                if (sf[e] > bv) { bv = sf[e]; best = e; }
            }
            used[best] = true;
            sel[kk] = best;
        }
        float wsum = 0.f, wv[TOPK_];
        for (int kk = 0; kk < TOPK_; kk++) { wv[kk] = sc[sel[kk]]; wsum += wv[kk]; }
        for (int kk = 0; kk < TOPK_; kk++) {
            ids[t*TOPK_ + kk]  = sel[kk];
            wout[t*TOPK_ + kk] = wv[kk] / wsum;
        }
    }
}

// ---------------------------------------------------------------------------
// Counting sort of (token,slot) by expert. Single block.
// ---------------------------------------------------------------------------
__global__ __launch_bounds__(256) void sort_kernel(
    const int* __restrict__ ids, int* __restrict__ sorted_token,
    int* __restrict__ slotpos, int* __restrict__ offs)
{
    __shared__ int cnt[E_], start[E_];
    int tid = threadIdx.x;
    if (tid < E_) cnt[tid] = 0;
    __syncthreads();
    for (int i = tid; i < T_*TOPK_; i += blockDim.x) atomicAdd(&cnt[ids[i]], 1);
    __syncthreads();
    if (tid == 0) {
        int acc = 0;
        for (int e = 0; e < E_; e++) { offs[e] = acc; start[e] = acc; acc += cnt[e]; }
        offs[E_] = acc;
    }
    __syncthreads();
    for (int i = tid; i < T_*TOPK_; i += blockDim.x) {
        int e = ids[i];
        int pos = atomicAdd(&start[e], 1);
        sorted_token[pos] = i >> 2;
        slotpos[i] = pos;
    }
}

// ---------------------------------------------------------------------------
// act = silu(gu[:, :IM]) * gu[:, IM:]
// ---------------------------------------------------------------------------
__global__ __launch_bounds__(256) void silu_mul_kernel(
    const float* __restrict__ gu, float* __restrict__ out, int rows, int im)
{
    long long idx = (long long)blockIdx.x * blockDim.x + threadIdx.x;
    long long total = (long long)rows * im;
    if (idx >= total) return;
    long long r = idx / im;
    int j = (int)(idx - r * im);
    float a = gu[r*(2*im) + j];
    float b = gu[r*(2*im) + im + j];
    float s = a / (1.f + __expf(-a));
    out[idx] = s * b;
}

// ---------------------------------------------------------------------------
// out[t] = shared[t] + sum_k w[t,k] * slot_out[slotpos[t,k]]
// ---------------------------------------------------------------------------
__global__ __launch_bounds__(256) void combine_kernel(
    const float* __restrict__ shexp, const float* __restrict__ slot_out,
    const int* __restrict__ slotpos, const float* __restrict__ w,
    float* __restrict__ out)
{
    int t = blockIdx.x;
    int i = threadIdx.x;
    int p[TOPK_]; float wv[TOPK_];
    #pragma unroll
    for (int k = 0; k < TOPK_; k++) { p[k] = slotpos[t*TOPK_+k]; wv[k] = w[t*TOPK_+k]; }
    float4 acc = ((const float4*)(shexp + (long long)t*H_))[i];
    #pragma unroll
    for (int k = 0; k < TOPK_; k++) {
        float4 v = ((const float4*)(slot_out + (long long)p[k]*H_))[i];
        acc.x += wv[k]*v.x; acc.y += wv[k]*v.y; acc.z += wv[k]*v.z; acc.w += wv[k]*v.w;
    }
    ((float4*)(out + (long long)t*H_))[i] = acc;
}

// ---------------------------------------------------------------------------
// Launch
// ---------------------------------------------------------------------------
extern "C" void kernel_launch(void* const* d_in, const int* in_sizes, int n_in,
                              void* d_out, int out_size)
{
    const float* hidden    = (const float*)d_in[0];
    const float* residual  = (const float*)d_in[1];
    const float* in_ln_w   = (const float*)d_in[2];
    const float* post_ln_w = (const float*)d_in[3];
    const float* q_norm_w  = (const float*)d_in[4];
    const float* k_norm_w  = (const float*)d_in[5];
    const float* Wqkv      = (const float*)d_in[6];
    const float* Wo        = (const float*)d_in[7];
    const float* Wg        = (const float*)d_in[8];
    const float* gate_bias = (const float*)d_in[9];
    const float* Wgu       = (const float*)d_in[10];
    const float* Wd        = (const float*)d_in[11];
    const float* Wgu_sh    = (const float*)d_in[12];
    const float* Wd_sh     = (const float*)d_in[13];
    const int*   positions = (const int*)d_in[14];

    float* out_hidden = (float*)d_out;
    float* out_resid  = out_hidden + (size_t)T_ * H_;

    float *p_r1, *p_ln1, *p_qkv, *p_q, *p_k, *p_v, *p_att, *p_h2;
    float *p_w, *p_gu, *p_act, *p_slot, *p_gus, *p_actsh, *p_shared;
    int *p_ids, *p_sorted, *p_slotpos, *p_offs;
    cudaGetSymbolAddress((void**)&p_r1,      g_r1);
    cudaGetSymbolAddress((void**)&p_ln1,     g_ln1);
    cudaGetSymbolAddress((void**)&p_qkv,     g_qkv);
    cudaGetSymbolAddress((void**)&p_q,       g_q);
    cudaGetSymbolAddress((void**)&p_k,       g_k);
    cudaGetSymbolAddress((void**)&p_v,       g_v);
    cudaGetSymbolAddress((void**)&p_att,     g_att);
    cudaGetSymbolAddress((void**)&p_h2,      g_h2);
    cudaGetSymbolAddress((void**)&p_w,       g_w);
    cudaGetSymbolAddress((void**)&p_ids,     g_ids);
    cudaGetSymbolAddress((void**)&p_sorted,  g_sorted);
    cudaGetSymbolAddress((void**)&p_slotpos, g_slotpos);
    cudaGetSymbolAddress((void**)&p_offs,    g_offs);
    cudaGetSymbolAddress((void**)&p_gu,      g_gu);
    cudaGetSymbolAddress((void**)&p_act,     g_actbuf);
    cudaGetSymbolAddress((void**)&p_slot,    g_slot);
    cudaGetSymbolAddress((void**)&p_gus,     g_gus);
    cudaGetSymbolAddress((void**)&p_actsh,   g_actsh);
    cudaGetSymbolAddress((void**)&p_shared,  g_shared);

    // 1) r1 = hidden + residual ; ln1 = rms(r1)*in_ln_w
    add_rms_kernel<<<T_, 256>>>(hidden, residual, in_ln_w, p_r1, p_ln1);

    // 2) qkv = ln1 @ Wqkv
    sgemm_kernel<false,false,false><<<dim3(1536/128, T_/128, 1), 256>>>(
        p_ln1, Wqkv, p_qkv, nullptr, T_, 1536, H_, nullptr, nullptr, 0);

    // 3) per-head rms + rope
    qknorm_rope_kernel<<<T_, 256>>>(p_qkv, q_norm_w, k_norm_w, positions,
                                    p_q, p_k, p_v);

    // 4) attention
    attn_kernel<<<dim3(T_/128, NH_), 128>>>(p_q, p_k, p_v, p_att);

    // 5) r2 = att @ Wo + r1  -> out_resid (second half of d_out)
    sgemm_kernel<false,false,true><<<dim3(H_/128, T_/128, 1), 256>>>(
        p_att, Wo, out_resid, p_r1, T_, H_, H_, nullptr, nullptr, 0);

    // 6) h2 = rms(r2)*post_ln_w
    add_rms_kernel<<<T_, 256>>>(out_resid, nullptr, post_ln_w, nullptr, p_h2);

    // 7) router
    router_kernel<<<T_/4, 128>>>(p_h2, Wg, gate_bias, p_ids, p_w);

    // 8) counting sort by expert
    sort_kernel<<<1, 256>>>(p_ids, p_sorted, p_slotpos, p_offs);

    // 9) routed up-proj (gathered, segmented): gu = h2[tok] @ Wgu[e]
    sgemm_kernel<true,true,false><<<dim3(2*IM_/128, T_/128, E_), 256>>>(
        p_h2, Wgu, p_gu, nullptr, 0, 2*IM_, H_, p_sorted, p_offs,
        (long long)H_ * 2*IM_);

    // 10) silu-mul for routed
    silu_mul_kernel<<<(T_*TOPK_*IM_ + 255)/256, 256>>>(p_gu, p_act, T_*TOPK_, IM_);

    // 11) routed down-proj (segmented): slot = act @ Wd[e]
    sgemm_kernel<true,false,false><<<dim3(H_/128, T_/128, E_), 256>>>(
        p_act, Wd, p_slot, nullptr, 0, H_, IM_, nullptr, p_offs,
        (long long)IM_ * H_);

    // 12) shared expert up
    sgemm_kernel<false,false,false><<<dim3(2*ISH_/128, T_/128, 1), 256>>>(
        p_h2, Wgu_sh, p_gus, nullptr, T_, 2*ISH_, H_, nullptr, nullptr, 0);

    // 13) silu-mul shared
    silu_mul_kernel<<<(T_*ISH_ + 255)/256, 256>>>(p_gus, p_actsh, T_, ISH_);

    // 14) shared expert down
    sgemm_kernel<false,false,false><<<dim3(H_/128, T_/128, 1), 256>>>(
        p_actsh, Wd_sh, p_shared, nullptr, T_, H_, ISH_, nullptr, nullptr, 0);

    // 15) out_hidden = shared + sum_k w_k * slot_out
    combine_kernel<<<T_, 256>>>(p_shared, p_slot, p_slotpos, p_w, out_hidden);
}

// round 4
// speedup vs baseline: 1.5561x; 1.5561x over previous
#include <cuda_runtime.h>
#include <cuda_bf16.h>
#include <math.h>
#include <stdint.h>

// ---------------------------------------------------------------------------
// Problem constants
// ---------------------------------------------------------------------------
#define T_   2048
#define H_   1024
#define NH_  16
#define NKV_ 4
#define HD_  64
#define E_   32
#define TOPK_ 4
#define NG_  4
#define TG_  2
#define IM_  384
#define ISH_ 384
#define ROT_ 32      // HD/2
#define EPS_ 1e-5f

// ---------------------------------------------------------------------------
// Scratch (device globals — allocation-free per harness rules)
// ---------------------------------------------------------------------------
__device__ float g_r1     [T_*H_];
__device__ float g_ln1    [T_*H_];
__device__ float g_qkv    [T_*1536];
__device__ float g_q      [T_*NH_*HD_];
__device__ float g_k      [T_*NKV_*HD_];
__device__ float g_v      [T_*NKV_*HD_];
__device__ float g_att    [T_*H_];
__device__ float g_h2     [T_*H_];
__device__ float g_w      [T_*TOPK_];
__device__ int   g_ids    [T_*TOPK_];
__device__ int   g_sorted [T_*TOPK_];
__device__ int   g_slotpos[T_*TOPK_];
__device__ int   g_offs   [E_+1];
__device__ float g_gu     [T_*TOPK_*2*IM_];
__device__ float g_actbuf [T_*TOPK_*IM_];
__device__ float g_slot   [T_*TOPK_*H_];
__device__ float g_gus    [T_*2*ISH_];
__device__ float g_actsh  [T_*ISH_];
__device__ float g_shared [T_*H_];

// ---------------------------------------------------------------------------
// Helpers
// ---------------------------------------------------------------------------
__device__ __forceinline__ float to_tf32(float x) {
    uint32_t u;
    asm("cvt.rna.tf32.f32 %0, %1;" : "=r"(u) : "f"(x));
    return __uint_as_float(u);
}

#define MMA_TF32(d0,d1,d2,d3,a0,a1,a2,a3,b0,b1)                               \
    asm volatile(                                                             \
        "mma.sync.aligned.m16n8k8.row.col.f32.tf32.tf32.f32 "                 \
        "{%0,%1,%2,%3},{%4,%5,%6,%7},{%8,%9},{%0,%1,%2,%3};"                  \
        : "+f"(d0), "+f"(d1), "+f"(d2), "+f"(d3)                              \
        : "r"(a0), "r"(a1), "r"(a2), "r"(a3), "r"(b0), "r"(b1))

// ---------------------------------------------------------------------------
// add + RMSNorm (row per block, 256 threads, float4). b / resid optional.
// ---------------------------------------------------------------------------
__global__ __launch_bounds__(256) void add_rms_kernel(
    const float* __restrict__ a, const float* __restrict__ b,
    const float* __restrict__ w, float* __restrict__ resid,
    float* __restrict__ out)
{
    int t = blockIdx.x;
    int i = threadIdx.x;
    float4 va = ((const float4*)(a + (long long)t*H_))[i];
    if (b) {
        float4 vb = ((const float4*)(b + (long long)t*H_))[i];
        va.x += vb.x; va.y += vb.y; va.z += vb.z; va.w += vb.w;
    }
    if (resid) ((float4*)(resid + (long long)t*H_))[i] = va;
    float ss = va.x*va.x + va.y*va.y + va.z*va.z + va.w*va.w;
    __shared__ float sred[8];
    #pragma unroll
    for (int off = 16; off; off >>= 1) ss += __shfl_xor_sync(0xffffffffu, ss, off);
    if ((i & 31) == 0) sred[i >> 5] = ss;
    __syncthreads();
    if (i < 8) {
        float v = sred[i];
        #pragma unroll
        for (int off = 4; off; off >>= 1) v += __shfl_xor_sync(0xffu, v, off);
        if (i == 0) sred[0] = v;
    }
    __syncthreads();
    float rs = rsqrtf(sred[0] / (float)H_ + EPS_);
    float4 vw = ((const float4*)w)[i];
    va.x *= rs * vw.x; va.y *= rs * vw.y; va.z *= rs * vw.z; va.w *= rs * vw.w;
    ((float4*)(out + (long long)t*H_))[i] = va;
}

// ---------------------------------------------------------------------------
// fp32 SGEMM (used only for routing-critical GEMMs: QKV, O-proj).
// ---------------------------------------------------------------------------
template<bool ADD>
__global__ __launch_bounds__(256) void sgemm_kernel(
    const float* __restrict__ A, const float* __restrict__ B,
    float* __restrict__ C, const float* __restrict__ addsrc,
    int M, int N, int K)
{
    constexpr int BM = 128, BN = 128, BK = 8, TM = 8, TN = 8;
    __shared__ float As[BK][BM];
    __shared__ float Bs[BK][BN];

    int row0 = blockIdx.y * BM;
    int col0 = blockIdx.x * BN;

    int tid  = threadIdx.x;
    int aRow = tid >> 1;
    int aCol = (tid & 1) * 4;
    int bRow = tid >> 5;
    int bCol = (tid & 31) * 4;
    int ty   = tid >> 4;
    int tx   = tid & 15;

    const float* Aptr = A + (long long)(row0 + aRow) * K;

    float acc[TM][TN];
    #pragma unroll
    for (int i = 0; i < TM; i++)
        #pragma unroll
        for (int j = 0; j < TN; j++) acc[i][j] = 0.f;

    float regM[TM], regN[TN];

    for (int k0 = 0; k0 < K; k0 += BK) {
        float4 av = *reinterpret_cast<const float4*>(Aptr + k0 + aCol);
        As[aCol+0][aRow] = av.x;
        As[aCol+1][aRow] = av.y;
        As[aCol+2][aRow] = av.z;
        As[aCol+3][aRow] = av.w;
        float4 bv = *reinterpret_cast<const float4*>(
            B + (long long)(k0 + bRow) * N + col0 + bCol);
        *reinterpret_cast<float4*>(&Bs[bRow][bCol]) = bv;
        __syncthreads();
        #pragma unroll
        for (int k = 0; k < BK; k++) {
            #pragma unroll
            for (int i = 0; i < TM; i++) regM[i] = As[k][ty*TM + i];
            #pragma unroll
            for (int j = 0; j < TN; j++) regN[j] = Bs[k][tx*TN + j];
            #pragma unroll
            for (int i = 0; i < TM; i++)
                #pragma unroll
                for (int j = 0; j < TN; j++)
                    acc[i][j] += regM[i] * regN[j];
        }
        __syncthreads();
    }

    #pragma unroll
    for (int i = 0; i < TM; i++) {
        int r = row0 + ty*TM + i;
        float* Crow = C + (long long)r * N + col0 + tx*TN;
        #pragma unroll
        for (int j = 0; j < TN; j += 4) {
            float4 v = make_float4(acc[i][j], acc[i][j+1], acc[i][j+2], acc[i][j+3]);
            if (ADD) {
                float4 a4 = *reinterpret_cast<const float4*>(
                    addsrc + (long long)r * N + col0 + tx*TN + j);
                v.x += a4.x; v.y += a4.y; v.z += a4.z; v.w += a4.w;
            }
            *reinterpret_cast<float4*>(Crow + j) = v;
        }
    }
}

// ---------------------------------------------------------------------------
// tf32 tensor-core GEMM (mma.sync m16n8k8), 128x128x16 tile, 256 threads.
//   SEG:    grid.z = expert; rows in [segoffs[z], segoffs[z+1]); B += z*bStride
//   GATHER: A row index from gather[globalRow]
// Used only for MoE GEMMs (downstream of routing decisions).
// ---------------------------------------------------------------------------
template<bool SEG, bool GATHER>
__global__ __launch_bounds__(256) void tf32gemm_kernel(
    const float* __restrict__ A, const float* __restrict__ Bbase,
    float* __restrict__ C, int M, int N, int K,
    const int* __restrict__ gather, const int* __restrict__ segoffs,
    long long bStride)
{
    constexpr int BM = 128, BN = 128, BK = 16;
    __shared__ float As[BM][BK + 4];    // row-major, padded
    __shared__ float Bs[BK][BN + 8];

    int rowBeg, rowEnd, z = 0;
    if (SEG) {
        z = blockIdx.z;
        rowBeg = segoffs[z];
        rowEnd = segoffs[z+1];
    } else {
        rowBeg = 0;
        rowEnd = M;
    }
    int row0 = rowBeg + blockIdx.y * BM;
    if (row0 >= rowEnd) return;
    int col0 = blockIdx.x * BN;
    const float* B = SEG ? (Bbase + (long long)z * bStride) : Bbase;

    int tid = threadIdx.x, lane = tid & 31, warp = tid >> 5;
    int grp = lane >> 2, t4 = lane & 3;
    int wm = (warp >> 2) * 64;      // warp row offset
    int wn = (warp & 3) * 32;       // warp col offset

    int ar = tid >> 2, av = tid & 3;
    int r0g = row0 + ar, r1g = row0 + ar + 64;
    bool v0 = r0g < rowEnd, v1 = r1g < rowEnd;
    long long sr0 = GATHER ? (v0 ? gather[r0g] : 0) : (v0 ? (long long)r0g : 0);
    long long sr1 = GATHER ? (v1 ? gather[r1g] : 0) : (v1 ? (long long)r1g : 0);
    int bk = tid >> 4, bn = tid & 15;

    float acc[4][4][4];
    #pragma unroll
    for (int mt = 0; mt < 4; mt++)
        #pragma unroll
        for (int nt = 0; nt < 4; nt++)
            #pragma unroll
            for (int c = 0; c < 4; c++) acc[mt][nt][c] = 0.f;

    for (int k0 = 0; k0 < K; k0 += BK) {
        float4 a0 = make_float4(0.f,0.f,0.f,0.f), a1 = a0;
        if (v0) a0 = *reinterpret_cast<const float4*>(A + sr0*K + k0 + av*4);
        if (v1) a1 = *reinterpret_cast<const float4*>(A + sr1*K + k0 + av*4);
        As[ar   ][av*4+0] = to_tf32(a0.x);
        As[ar   ][av*4+1] = to_tf32(a0.y);
        As[ar   ][av*4+2] = to_tf32(a0.z);
        As[ar   ][av*4+3] = to_tf32(a0.w);
        As[ar+64][av*4+0] = to_tf32(a1.x);
        As[ar+64][av*4+1] = to_tf32(a1.y);
        As[ar+64][av*4+2] = to_tf32(a1.z);
        As[ar+64][av*4+3] = to_tf32(a1.w);

        float4 b0 = *reinterpret_cast<const float4*>(
            B + (long long)(k0 + bk) * N + col0 + bn*4);
        float4 b1 = *reinterpret_cast<const float4*>(
            B + (long long)(k0 + bk) * N + col0 + bn*4 + 64);
        Bs[bk][bn*4+0]  = to_tf32(b0.x);
        Bs[bk][bn*4+1]  = to_tf32(b0.y);
        Bs[bk][bn*4+2]  = to_tf32(b0.z);
        Bs[bk][bn*4+3]  = to_tf32(b0.w);
        Bs[bk][bn*4+64] = to_tf32(b1.x);
        Bs[bk][bn*4+65] = to_tf32(b1.y);
        Bs[bk][bn*4+66] = to_tf32(b1.z);
        Bs[bk][bn*4+67] = to_tf32(b1.w);
        __syncthreads();

        #pragma unroll
        for (int ks = 0; ks < 2; ks++) {
            uint32_t af[4][4];
            #pragma unroll
            for (int mt = 0; mt < 4; mt++) {
                int r = wm + mt*16;
                af[mt][0] = __float_as_uint(As[r+grp  ][ks*8 + t4    ]);
                af[mt][1] = __float_as_uint(As[r+grp+8][ks*8 + t4    ]);
                af[mt][2] = __float_as_uint(As[r+grp  ][ks*8 + t4 + 4]);
                af[mt][3] = __float_as_uint(As[r+grp+8][ks*8 + t4 + 4]);
            }
            uint32_t bf[4][2];
            #pragma unroll
            for (int nt = 0; nt < 4; nt++) {
                bf[nt][0] = __float_as_uint(Bs[ks*8 + t4    ][wn + nt*8 + grp]);
                bf[nt][1] = __float_as_uint(Bs[ks*8 + t4 + 4][wn + nt*8 + grp]);
            }
            #pragma unroll
            for (int mt = 0; mt < 4; mt++)
                #pragma unroll
                for (int nt = 0; nt < 4; nt++)
                    MMA_TF32(acc[mt][nt][0], acc[mt][nt][1],
                             acc[mt][nt][2], acc[mt][nt][3],
                             af[mt][0], af[mt][1], af[mt][2], af[mt][3],
                             bf[nt][0], bf[nt][1]);
        }
        __syncthreads();
    }

    #pragma unroll
    for (int mt = 0; mt < 4; mt++) {
        int r0 = row0 + wm + mt*16 + grp;
        int r1 = r0 + 8;
        #pragma unroll
        for (int nt = 0; nt < 4; nt++) {
            int col = col0 + wn + nt*8 + 2*t4;
            if (r0 < rowEnd) {
                float2 v = make_float2(acc[mt][nt][0], acc[mt][nt][1]);
                *reinterpret_cast<float2*>(C + (long long)r0*N + col) = v;
            }
            if (r1 < rowEnd) {
                float2 v = make_float2(acc[mt][nt][2], acc[mt][nt][3]);
                *reinterpret_cast<float2*>(C + (long long)r1*N + col) = v;
            }
        }
    }
}

// ---------------------------------------------------------------------------
// Per-head RMSNorm + RoPE for q and k; copy v. Block = 1 token, 256 threads.
// ---------------------------------------------------------------------------
__global__ __launch_bounds__(256) void qknorm_rope_kernel(
    const float* __restrict__ qkv,
    const float* __restrict__ qw, const float* __restrict__ kw,
    const int* __restrict__ positions,
    float* __restrict__ Qo, float* __restrict__ Ko, float* __restrict__ Vo)
{
    int t = blockIdx.x;
    int warp = threadIdx.x >> 5, lane = threadIdx.x & 31;
    float p = (float)positions[t];

    for (int vec = warp; vec < NH_ + NKV_; vec += 8) {
        bool isq = vec < NH_;
        const float* src = qkv + (long long)t*1536 + vec*HD_;
        float x0 = src[lane], x1 = src[lane + 32];
        float ss = x0*x0 + x1*x1;
        #pragma unroll
        for (int off = 16; off; off >>= 1) ss += __shfl_xor_sync(0xffffffffu, ss, off);
        float r = rsqrtf(ss / (float)HD_ + EPS_);
        const float* w = isq ? qw : kw;
        x0 = x0 * r * w[lane];
        x1 = x1 * r * w[lane + 32];
        int i = lane & 15;
        float inv = powf(10000.f, -((float)(2*i) / (float)ROT_));
        float ang = p * inv;
        float c = cosf(ang), s = sinf(ang);
        float partner = __shfl_xor_sync(0xffffffffu, x0, 16);
        float y0;
        if (lane < 16) y0 = x0 * c - partner * s;
        else           y0 = partner * s + x0 * c;
        x0 = y0;
        float* dst = isq ? (Qo + ((long long)t*NH_ + vec)*HD_)
                         : (Ko + ((long long)t*NKV_ + (vec - NH_))*HD_);
        dst[lane] = x0;
        dst[lane + 32] = x1;
    }
    for (int i = threadIdx.x; i < NKV_*HD_; i += blockDim.x)
        Vo[(long long)t*NKV_*HD_ + i] = qkv[(long long)t*1536 + 1280 + i];
}

// ---------------------------------------------------------------------------
// Causal attention, online softmax. 2 threads per query (split head dim),
// batch-of-8 keys per rescale. Block=128 thr -> 64 queries; grid=(T/64, NH).
// All warp-collective shuffles execute with warp-uniform trip counts:
// the sb-loop iterates to the WARP's max smax; over-iterated steps are
// exact no-ops via the sc[j] = -1e30 predication (pp=0, corr=1).
// ---------------------------------------------------------------------------
__global__ __launch_bounds__(128) void attn_kernel(
    const float* __restrict__ Q, const float* __restrict__ Kc,
    const float* __restrict__ Vc, float* __restrict__ O)
{
    const int h = blockIdx.y;
    const int kvh = h >> 2;
    const int qb = ((int)gridDim.x - 1 - (int)blockIdx.x) * 64;
    const int qi = threadIdx.x >> 1;        // local query 0..63
    const int half = threadIdx.x & 1;       // which 32-dim half
    const int t = qb + qi;
    // highest query index owned by this warp (lanes are consecutive)
    const int tWarpMax = qb + ((threadIdx.x | 31) >> 1);

    __shared__ float Ks[64][64];
    __shared__ float Vs[64][64];

    float4 q4[8], o4[8];
    {
        const float4* qp = (const float4*)&Q[((long long)t*NH_ + h)*HD_ + half*32];
        #pragma unroll
        for (int c = 0; c < 8; c++) q4[c] = qp[c];
        #pragma unroll
        for (int c = 0; c < 8; c++) o4[c] = make_float4(0.f,0.f,0.f,0.f);
    }
    float m = -1e30f, l = 0.f;

    const int nTiles = qb/64 + 1;
    for (int jt = 0; jt < nTiles; jt++) {
        int s0 = jt * 64;
        for (int idx = threadIdx.x; idx < 64*16; idx += 128) {
            int r = idx >> 4;
            int c = (idx & 15) * 4;
            *(float4*)&Ks[r][c] = *(const float4*)&Kc[((long long)(s0+r)*NKV_ + kvh)*HD_ + c];
            *(float4*)&Vs[r][c] = *(const float4*)&Vc[((long long)(s0+r)*NKV_ + kvh)*HD_ + c];
        }
        __syncthreads();
        int smax = t - s0 + 1;              // per-thread causal bound
        if (smax > 64) smax = 64;
        int warpSmax = tWarpMax - s0 + 1;   // warp-uniform loop bound
        if (warpSmax > 64) warpSmax = 64;
        for (int sb = 0; sb < warpSmax; sb += 8) {
            float sc[8];
            #pragma unroll
            for (int j = 0; j < 8; j++) {
                int s = sb + j;
                const float4* kp = (const float4*)&Ks[s][half*32];
                float d = 0.f;
                #pragma unroll
                for (int c = 0; c < 8; c++) {
                    float4 kv = kp[c];
                    d += q4[c].x*kv.x + q4[c].y*kv.y + q4[c].z*kv.z + q4[c].w*kv.w;
                }
                d += __shfl_xor_sync(0xffffffffu, d, 1);
                sc[j] = (s < smax) ? d * 0.125f : -1e30f;
            }
            float bm = sc[0];
            #pragma unroll
            for (int j = 1; j < 8; j++) bm = fmaxf(bm, sc[j]);
            float mn = fmaxf(m, bm);
            float corr = __expf(m - mn);
            l *= corr;
            #pragma unroll
            for (int c = 0; c < 8; c++) {
                o4[c].x *= corr; o4[c].y *= corr; o4[c].z *= corr; o4[c].w *= corr;
            }
            #pragma unroll
            for (int j = 0; j < 8; j++) {
                float pp = __expf(sc[j] - mn);
                l += pp;
                const float4* vp = (const float4*)&Vs[sb+j][half*32];
                #pragma unroll
                for (int c = 0; c < 8; c++) {
                    float4 vv = vp[c];
                    o4[c].x += pp * vv.x; o4[c].y += pp * vv.y;
                    o4[c].z += pp * vv.z; o4[c].w += pp * vv.w;
                }
            }
            m = mn;
        }
        __syncthreads();
    }
    float invl = 1.f / l;
    float4* op = (float4*)&O[(long long)t*H_ + h*HD_ + half*32];
    #pragma unroll
    for (int c = 0; c < 8; c++) {
        o4[c].x *= invl; o4[c].y *= invl; o4[c].z *= invl; o4[c].w *= invl;
        op[c] = o4[c];
    }
}

// ---------------------------------------------------------------------------
// Router: warp per token. Exact replication of group top-k routing (fp32).
// ---------------------------------------------------------------------------
__global__ __launch_bounds__(128) void router_kernel(
    const float* __restrict__ h2, const float* __restrict__ Wg,
    const float* __restrict__ bias, int* __restrict__ ids,
    float* __restrict__ wout)
{
    int warp = threadIdx.x >> 5, lane = threadIdx.x & 31;
    int t = blockIdx.x * 4 + warp;
    const float* h = h2 + (long long)t * H_;
    float acc = 0.f;
    for (int k = 0; k < H_; k++) acc += __ldg(&h[k]) * __ldg(&Wg[k*E_ + lane]);
    float scr = 1.f / (1.f + expf(-acc));
    __shared__ float s_scr[4][E_];
    __shared__ float s_sfc[4][E_];
    s_scr[warp][lane] = scr;
    s_sfc[warp][lane] = scr + bias[lane];
    __syncwarp();
    if (lane == 0) {
        float* sc = s_scr[warp];
        float* sf = s_sfc[warp];
        float gs[NG_];
        for (int g = 0; g < NG_; g++) {
            float m1 = -1e30f, m2 = -1e30f;
            for (int j = 0; j < E_/NG_; j++) {
                float v = sf[g*(E_/NG_) + j];
                if (v > m1) { m2 = m1; m1 = v; }
                else if (v > m2) { m2 = v; }
            }
            gs[g] = m1 + m2;
        }
        int g1 = 0;
        for (int g = 1; g < NG_; g++) if (gs[g] > gs[g1]) g1 = g;
        int g2 = -1;
        for (int g = 0; g < NG_; g++) {
            if (g == g1) continue;
            if (g2 < 0 || gs[g] > gs[g2]) g2 = g;
        }
        bool used[E_];
        for (int e = 0; e < E_; e++) used[e] = false;
        int sel[TOPK_];
        for (int kk = 0; kk < TOPK_; kk++) {
            int best = -1; float bv = -1e30f;
            for (int e = 0; e < E_; e++) {
                int g = e >> 3;
                if ((g != g1 && g != g2) || used[e]) continue;
                if (sf[e] > bv) { bv = sf[e]; best = e; }
            }
            used[best] = true;
            sel[kk] = best;
        }
        float wsum = 0.f, wv[TOPK_];
        for (int kk = 0; kk < TOPK_; kk++) { wv[kk] = sc[sel[kk]]; wsum += wv[kk]; }
        for (int kk = 0; kk < TOPK_; kk++) {
            ids[t*TOPK_ + kk]  = sel[kk];
            wout[t*TOPK_ + kk] = wv[kk] / wsum;
        }
    }
}

// ---------------------------------------------------------------------------
// Counting sort of (token,slot) by expert. Single block.
// ---------------------------------------------------------------------------
__global__ __launch_bounds__(256) void sort_kernel(
    const int* __restrict__ ids, int* __restrict__ sorted_token,
    int* __restrict__ slotpos, int* __restrict__ offs)
{
    __shared__ int cnt[E_], start[E_];
    int tid = threadIdx.x;
    if (tid < E_) cnt[tid] = 0;
    __syncthreads();
    for (int i = tid; i < T_*TOPK_; i += blockDim.x) atomicAdd(&cnt[ids[i]], 1);
    __syncthreads();
    if (tid == 0) {
        int acc = 0;
        for (int e = 0; e < E_; e++) { offs[e] = acc; start[e] = acc; acc += cnt[e]; }
        offs[E_] = acc;
    }
    __syncthreads();
    for (int i = tid; i < T_*TOPK_; i += blockDim.x) {
        int e = ids[i];
        int pos = atomicAdd(&start[e], 1);
        sorted_token[pos] = i >> 2;
        slotpos[i] = pos;
    }
}

// ---------------------------------------------------------------------------
// act = silu(gu[:, :IM]) * gu[:, IM:]
// ---------------------------------------------------------------------------
__global__ __launch_bounds__(256) void silu_mul_kernel(
    const float* __restrict__ gu, float* __restrict__ out, int rows, int im)
{
    long long idx = (long long)blockIdx.x * blockDim.x + threadIdx.x;
    long long total = (long long)rows * im;
    if (idx >= total) return;
    long long r = idx / im;
    int j = (int)(idx - r * im);
    float a = gu[r*(2*im) + j];
    float b = gu[r*(2*im) + im + j];
    float s = a / (1.f + __expf(-a));
    out[idx] = s * b;
}

// ---------------------------------------------------------------------------
// out[t] = shared[t] + sum_k w[t,k] * slot_out[slotpos[t,k]]
// ---------------------------------------------------------------------------
__global__ __launch_bounds__(256) void combine_kernel(
    const float* __restrict__ shexp, const float* __restrict__ slot_out,
    const int* __restrict__ slotpos, const float* __restrict__ w,
    float* __restrict__ out)
{
    int t = blockIdx.x;
    int i = threadIdx.x;
    int p[TOPK_]; float wv[TOPK_];
    #pragma unroll
    for (int k = 0; k < TOPK_; k++) { p[k] = slotpos[t*TOPK_+k]; wv[k] = w[t*TOPK_+k]; }
    float4 acc = ((const float4*)(shexp + (long long)t*H_))[i];
    #pragma unroll
    for (int k = 0; k < TOPK_; k++) {
        float4 v = ((const float4*)(slot_out + (long long)p[k]*H_))[i];
        acc.x += wv[k]*v.x; acc.y += wv[k]*v.y; acc.z += wv[k]*v.z; acc.w += wv[k]*v.w;
    }
    ((float4*)(out + (long long)t*H_))[i] = acc;
}

// ---------------------------------------------------------------------------
// Launch
// ---------------------------------------------------------------------------
extern "C" void kernel_launch(void* const* d_in, const int* in_sizes, int n_in,
                              void* d_out, int out_size)
{
    const float* hidden    = (const float*)d_in[0];
    const float* residual  = (const float*)d_in[1];
    const float* in_ln_w   = (const float*)d_in[2];
    const float* post_ln_w = (const float*)d_in[3];
    const float* q_norm_w  = (const float*)d_in[4];
    const float* k_norm_w  = (const float*)d_in[5];
    const float* Wqkv      = (const float*)d_in[6];
    const float* Wo        = (const float*)d_in[7];
    const float* Wg        = (const float*)d_in[8];
    const float* gate_bias = (const float*)d_in[9];
    const float* Wgu       = (const float*)d_in[10];
    const float* Wd        = (const float*)d_in[11];
    const float* Wgu_sh    = (const float*)d_in[12];
    const float* Wd_sh     = (const float*)d_in[13];
    const int*   positions = (const int*)d_in[14];

    float* out_hidden = (float*)d_out;
    float* out_resid  = out_hidden + (size_t)T_ * H_;

    float *p_r1, *p_ln1, *p_qkv, *p_q, *p_k, *p_v, *p_att, *p_h2;
    float *p_w, *p_gu, *p_act, *p_slot, *p_gus, *p_actsh, *p_shared;
    int *p_ids, *p_sorted, *p_slotpos, *p_offs;
    cudaGetSymbolAddress((void**)&p_r1,      g_r1);
    cudaGetSymbolAddress((void**)&p_ln1,     g_ln1);
    cudaGetSymbolAddress((void**)&p_qkv,     g_qkv);
    cudaGetSymbolAddress((void**)&p_q,       g_q);
    cudaGetSymbolAddress((void**)&p_k,       g_k);
    cudaGetSymbolAddress((void**)&p_v,       g_v);
    cudaGetSymbolAddress((void**)&p_att,     g_att);
    cudaGetSymbolAddress((void**)&p_h2,      g_h2);
    cudaGetSymbolAddress((void**)&p_w,       g_w);
    cudaGetSymbolAddress((void**)&p_ids,     g_ids);
    cudaGetSymbolAddress((void**)&p_sorted,  g_sorted);
    cudaGetSymbolAddress((void**)&p_slotpos, g_slotpos);
    cudaGetSymbolAddress((void**)&p_offs,    g_offs);
    cudaGetSymbolAddress((void**)&p_gu,      g_gu);
    cudaGetSymbolAddress((void**)&p_act,     g_actbuf);
    cudaGetSymbolAddress((void**)&p_slot,    g_slot);
    cudaGetSymbolAddress((void**)&p_gus,     g_gus);
    cudaGetSymbolAddress((void**)&p_actsh,   g_actsh);
    cudaGetSymbolAddress((void**)&p_shared,  g_shared);

    // 1) r1 = hidden + residual ; ln1 = rms(r1)*in_ln_w
    add_rms_kernel<<<T_, 256>>>(hidden, residual, in_ln_w, p_r1, p_ln1);

    // 2) qkv = ln1 @ Wqkv  (fp32: routing-critical)
    sgemm_kernel<false><<<dim3(1536/128, T_/128), 256>>>(
        p_ln1, Wqkv, p_qkv, nullptr, T_, 1536, H_);

    // 3) per-head rms + rope
    qknorm_rope_kernel<<<T_, 256>>>(p_qkv, q_norm_w, k_norm_w, positions,
                                    p_q, p_k, p_v);

    // 4) attention (fp32: routing-critical)
    attn_kernel<<<dim3(T_/64, NH_), 128>>>(p_q, p_k, p_v, p_att);

    // 5) r2 = att @ Wo + r1  -> out_resid (fp32: routing-critical)
    sgemm_kernel<true><<<dim3(H_/128, T_/128), 256>>>(
        p_att, Wo, out_resid, p_r1, T_, H_, H_);

    // 6) h2 = rms(r2)*post_ln_w
    add_rms_kernel<<<T_, 256>>>(out_resid, nullptr, post_ln_w, nullptr, p_h2);

    // 7) router (fp32 exact)
    router_kernel<<<T_/4, 128>>>(p_h2, Wg, gate_bias, p_ids, p_w);

    // 8) counting sort by expert
    sort_kernel<<<1, 256>>>(p_ids, p_sorted, p_slotpos, p_offs);

    // 9) routed up-proj (tf32 TC, gathered+segmented): gu = h2[tok] @ Wgu[e]
    //    grid.y = 64 covers worst-case 8192 rows in one expert (empty blocks exit)
    tf32gemm_kernel<true,true><<<dim3(2*IM_/128, 64, E_), 256>>>(
        p_h2, Wgu, p_gu, 0, 2*IM_, H_, p_sorted, p_offs,
        (long long)H_ * 2*IM_);

    // 10) silu-mul for routed
    silu_mul_kernel<<<(T_*TOPK_*IM_ + 255)/256, 256>>>(p_gu, p_act, T_*TOPK_, IM_);

    // 11) routed down-proj (tf32 TC, segmented): slot = act @ Wd[e]
    tf32gemm_kernel<true,false><<<dim3(H_/128, 64, E_), 256>>>(
        p_act, Wd, p_slot, 0, H_, IM_, nullptr, p_offs,
        (long long)IM_ * H_);

    // 12) shared expert up (tf32 TC)
    tf32gemm_kernel<false,false><<<dim3(2*ISH_/128, T_/128), 256>>>(
        p_h2, Wgu_sh, p_gus, T_, 2*ISH_, H_, nullptr, nullptr, 0);

    // 13) silu-mul shared
    silu_mul_kernel<<<(T_*ISH_ + 255)/256, 256>>>(p_gus, p_actsh, T_, ISH_);

    // 14) shared expert down (tf32 TC)
    tf32gemm_kernel<false,false><<<dim3(H_/128, T_/128), 256>>>(
        p_actsh, Wd_sh, p_shared, T_, H_, ISH_, nullptr, nullptr, 0);

    // 15) out_hidden = shared + sum_k w_k * slot_out
    combine_kernel<<<T_, 256>>>(p_shared, p_slot, p_slotpos, p_w, out_hidden);
}

// round 6
// speedup vs baseline: 2.1870x; 1.4055x over previous
#include <cuda_runtime.h>
#include <cuda_bf16.h>
#include <math.h>
#include <stdint.h>

// ---------------------------------------------------------------------------
// Problem constants
// ---------------------------------------------------------------------------
#define T_   2048
#define H_   1024
#define NH_  16
#define NKV_ 4
#define HD_  64
#define E_   32
#define TOPK_ 4
#define NG_  4
#define TG_  2
#define IM_  384
#define ISH_ 384
#define ROT_ 32      // HD/2
#define EPS_ 1e-5f

// ---------------------------------------------------------------------------
// Scratch (device globals — allocation-free per harness rules)
// ---------------------------------------------------------------------------
__device__ float g_r1     [T_*H_];
__device__ float g_ln1    [T_*H_];
__device__ float g_qkv    [T_*1536];
__device__ float g_q      [T_*NH_*HD_];
__device__ float g_k      [T_*NKV_*HD_];
__device__ float g_v      [T_*NKV_*HD_];
__device__ float g_att    [T_*H_];
__device__ float g_h2     [T_*H_];
__device__ float g_w      [T_*TOPK_];
__device__ int   g_ids    [T_*TOPK_];
__device__ int   g_sorted [T_*TOPK_];
__device__ int   g_slotpos[T_*TOPK_];
__device__ int   g_offs   [E_+1];
__device__ float g_gu     [T_*TOPK_*2*IM_];
__device__ float g_actbuf [T_*TOPK_*IM_];
__device__ float g_slot   [T_*TOPK_*H_];
__device__ float g_gus    [T_*2*ISH_];
__device__ float g_actsh  [T_*ISH_];
__device__ float g_shared [T_*H_];

// ---------------------------------------------------------------------------
// Helpers
// ---------------------------------------------------------------------------
__device__ __forceinline__ float to_tf32(float x) {
    uint32_t u;
    asm("cvt.rna.tf32.f32 %0, %1;" : "=r"(u) : "f"(x));
    return __uint_as_float(u);
}
__device__ __forceinline__ uint32_t tf32_bits(float x) {
    uint32_t u;
    asm("cvt.rna.tf32.f32 %0, %1;" : "=r"(u) : "f"(x));
    return u;
}

#define MMA_TF32(d0,d1,d2,d3,a0,a1,a2,a3,b0,b1)                               \
    asm volatile(                                                             \
        "mma.sync.aligned.m16n8k8.row.col.f32.tf32.tf32.f32 "                 \
        "{%0,%1,%2,%3},{%4,%5,%6,%7},{%8,%9},{%0,%1,%2,%3};"                  \
        : "+f"(d0), "+f"(d1), "+f"(d2), "+f"(d3)                              \
        : "r"(a0), "r"(a1), "r"(a2), "r"(a3), "r"(b0), "r"(b1))

// ---------------------------------------------------------------------------
// add + RMSNorm (row per block, 256 threads, float4). b / resid optional.
// ---------------------------------------------------------------------------
__global__ __launch_bounds__(256) void add_rms_kernel(
    const float* __restrict__ a, const float* __restrict__ b,
    const float* __restrict__ w, float* __restrict__ resid,
    float* __restrict__ out)
{
    int t = blockIdx.x;
    int i = threadIdx.x;
    float4 va = ((const float4*)(a + (long long)t*H_))[i];
    if (b) {
        float4 vb = ((const float4*)(b + (long long)t*H_))[i];
        va.x += vb.x; va.y += vb.y; va.z += vb.z; va.w += vb.w;
    }
    if (resid) ((float4*)(resid + (long long)t*H_))[i] = va;
    float ss = va.x*va.x + va.y*va.y + va.z*va.z + va.w*va.w;
    __shared__ float sred[8];
    #pragma unroll
    for (int off = 16; off; off >>= 1) ss += __shfl_xor_sync(0xffffffffu, ss, off);
    if ((i & 31) == 0) sred[i >> 5] = ss;
    __syncthreads();
    if (i < 8) {
        float v = sred[i];
        #pragma unroll
        for (int off = 4; off; off >>= 1) v += __shfl_xor_sync(0xffu, v, off);
        if (i == 0) sred[0] = v;
    }
    __syncthreads();
    float rs = rsqrtf(sred[0] / (float)H_ + EPS_);
    float4 vw = ((const float4*)w)[i];
    va.x *= rs * vw.x; va.y *= rs * vw.y; va.z *= rs * vw.z; va.w *= rs * vw.w;
    ((float4*)(out + (long long)t*H_))[i] = va;
}

// ---------------------------------------------------------------------------
// fp32 SGEMM (used only for routing-critical GEMMs: QKV, O-proj).
// ---------------------------------------------------------------------------
template<bool ADD>
__global__ __launch_bounds__(256) void sgemm_kernel(
    const float* __restrict__ A, const float* __restrict__ B,
    float* __restrict__ C, const float* __restrict__ addsrc,
    int M, int N, int K)
{
    constexpr int BM = 128, BN = 128, BK = 8, TM = 8, TN = 8;
    __shared__ float As[BK][BM];
    __shared__ float Bs[BK][BN];

    int row0 = blockIdx.y * BM;
    int col0 = blockIdx.x * BN;

    int tid  = threadIdx.x;
    int aRow = tid >> 1;
    int aCol = (tid & 1) * 4;
    int bRow = tid >> 5;
    int bCol = (tid & 31) * 4;
    int ty   = tid >> 4;
    int tx   = tid & 15;

    const float* Aptr = A + (long long)(row0 + aRow) * K;

    float acc[TM][TN];
    #pragma unroll
    for (int i = 0; i < TM; i++)
        #pragma unroll
        for (int j = 0; j < TN; j++) acc[i][j] = 0.f;

    float regM[TM], regN[TN];

    for (int k0 = 0; k0 < K; k0 += BK) {
        float4 av = *reinterpret_cast<const float4*>(Aptr + k0 + aCol);
        As[aCol+0][aRow] = av.x;
        As[aCol+1][aRow] = av.y;
        As[aCol+2][aRow] = av.z;
        As[aCol+3][aRow] = av.w;
        float4 bv = *reinterpret_cast<const float4*>(
            B + (long long)(k0 + bRow) * N + col0 + bCol);
        *reinterpret_cast<float4*>(&Bs[bRow][bCol]) = bv;
        __syncthreads();
        #pragma unroll
        for (int k = 0; k < BK; k++) {
            #pragma unroll
            for (int i = 0; i < TM; i++) regM[i] = As[k][ty*TM + i];
            #pragma unroll
            for (int j = 0; j < TN; j++) regN[j] = Bs[k][tx*TN + j];
            #pragma unroll
            for (int i = 0; i < TM; i++)
                #pragma unroll
                for (int j = 0; j < TN; j++)
                    acc[i][j] += regM[i] * regN[j];
        }
        __syncthreads();
    }

    #pragma unroll
    for (int i = 0; i < TM; i++) {
        int r = row0 + ty*TM + i;
        float* Crow = C + (long long)r * N + col0 + tx*TN;
        #pragma unroll
        for (int j = 0; j < TN; j += 4) {
            float4 v = make_float4(acc[i][j], acc[i][j+1], acc[i][j+2], acc[i][j+3]);
            if (ADD) {
                float4 a4 = *reinterpret_cast<const float4*>(
                    addsrc + (long long)r * N + col0 + tx*TN + j);
                v.x += a4.x; v.y += a4.y; v.z += a4.z; v.w += a4.w;
            }
            *reinterpret_cast<float4*>(Crow + j) = v;
        }
    }
}

// ---------------------------------------------------------------------------
// tf32 tensor-core GEMM (mma.sync m16n8k8), 128x128x16 tile, 256 threads.
// ---------------------------------------------------------------------------
template<bool SEG, bool GATHER>
__global__ __launch_bounds__(256) void tf32gemm_kernel(
    const float* __restrict__ A, const float* __restrict__ Bbase,
    float* __restrict__ C, int M, int N, int K,
    const int* __restrict__ gather, const int* __restrict__ segoffs,
    long long bStride)
{
    constexpr int BM = 128, BN = 128, BK = 16;
    __shared__ float As[BM][BK + 4];
    __shared__ float Bs[BK][BN + 8];

    int rowBeg, rowEnd, z = 0;
    if (SEG) {
        z = blockIdx.z;
        rowBeg = segoffs[z];
        rowEnd = segoffs[z+1];
    } else {
        rowBeg = 0;
        rowEnd = M;
    }
    int row0 = rowBeg + blockIdx.y * BM;
    if (row0 >= rowEnd) return;
    int col0 = blockIdx.x * BN;
    const float* B = SEG ? (Bbase + (long long)z * bStride) : Bbase;

    int tid = threadIdx.x, lane = tid & 31, warp = tid >> 5;
    int grp = lane >> 2, t4 = lane & 3;
    int wm = (warp >> 2) * 64;
    int wn = (warp & 3) * 32;

    int ar = tid >> 2, av = tid & 3;
    int r0g = row0 + ar, r1g = row0 + ar + 64;
    bool v0 = r0g < rowEnd, v1 = r1g < rowEnd;
    long long sr0 = GATHER ? (v0 ? gather[r0g] : 0) : (v0 ? (long long)r0g : 0);
    long long sr1 = GATHER ? (v1 ? gather[r1g] : 0) : (v1 ? (long long)r1g : 0);
    int bk = tid >> 4, bn = tid & 15;

    float acc[4][4][4];
    #pragma unroll
    for (int mt = 0; mt < 4; mt++)
        #pragma unroll
        for (int nt = 0; nt < 4; nt++)
            #pragma unroll
            for (int c = 0; c < 4; c++) acc[mt][nt][c] = 0.f;

    for (int k0 = 0; k0 < K; k0 += BK) {
        float4 a0 = make_float4(0.f,0.f,0.f,0.f), a1 = a0;
        if (v0) a0 = *reinterpret_cast<const float4*>(A + sr0*K + k0 + av*4);
        if (v1) a1 = *reinterpret_cast<const float4*>(A + sr1*K + k0 + av*4);
        As[ar   ][av*4+0] = to_tf32(a0.x);
        As[ar   ][av*4+1] = to_tf32(a0.y);
        As[ar   ][av*4+2] = to_tf32(a0.z);
        As[ar   ][av*4+3] = to_tf32(a0.w);
        As[ar+64][av*4+0] = to_tf32(a1.x);
        As[ar+64][av*4+1] = to_tf32(a1.y);
        As[ar+64][av*4+2] = to_tf32(a1.z);
        As[ar+64][av*4+3] = to_tf32(a1.w);

        float4 b0 = *reinterpret_cast<const float4*>(
            B + (long long)(k0 + bk) * N + col0 + bn*4);
        float4 b1 = *reinterpret_cast<const float4*>(
            B + (long long)(k0 + bk) * N + col0 + bn*4 + 64);
        Bs[bk][bn*4+0]  = to_tf32(b0.x);
        Bs[bk][bn*4+1]  = to_tf32(b0.y);
        Bs[bk][bn*4+2]  = to_tf32(b0.z);
        Bs[bk][bn*4+3]  = to_tf32(b0.w);
        Bs[bk][bn*4+64] = to_tf32(b1.x);
        Bs[bk][bn*4+65] = to_tf32(b1.y);
        Bs[bk][bn*4+66] = to_tf32(b1.z);
        Bs[bk][bn*4+67] = to_tf32(b1.w);
        __syncthreads();

        #pragma unroll
        for (int ks = 0; ks < 2; ks++) {
            uint32_t af[4][4];
            #pragma unroll
            for (int mt = 0; mt < 4; mt++) {
                int r = wm + mt*16;
                af[mt][0] = __float_as_uint(As[r+grp  ][ks*8 + t4    ]);
                af[mt][1] = __float_as_uint(As[r+grp+8][ks*8 + t4    ]);
                af[mt][2] = __float_as_uint(As[r+grp  ][ks*8 + t4 + 4]);
                af[mt][3] = __float_as_uint(As[r+grp+8][ks*8 + t4 + 4]);
            }
            uint32_t bf[4][2];
            #pragma unroll
            for (int nt = 0; nt < 4; nt++) {
                bf[nt][0] = __float_as_uint(Bs[ks*8 + t4    ][wn + nt*8 + grp]);
                bf[nt][1] = __float_as_uint(Bs[ks*8 + t4 + 4][wn + nt*8 + grp]);
            }
            #pragma unroll
            for (int mt = 0; mt < 4; mt++)
                #pragma unroll
                for (int nt = 0; nt < 4; nt++)
                    MMA_TF32(acc[mt][nt][0], acc[mt][nt][1],
                             acc[mt][nt][2], acc[mt][nt][3],
                             af[mt][0], af[mt][1], af[mt][2], af[mt][3],
                             bf[nt][0], bf[nt][1]);
        }
        __syncthreads();
    }

    #pragma unroll
    for (int mt = 0; mt < 4; mt++) {
        int r0 = row0 + wm + mt*16 + grp;
        int r1 = r0 + 8;
        #pragma unroll
        for (int nt = 0; nt < 4; nt++) {
            int col = col0 + wn + nt*8 + 2*t4;
            if (r0 < rowEnd) {
                float2 v = make_float2(acc[mt][nt][0], acc[mt][nt][1]);
                *reinterpret_cast<float2*>(C + (long long)r0*N + col) = v;
            }
            if (r1 < rowEnd) {
                float2 v = make_float2(acc[mt][nt][2], acc[mt][nt][3]);
                *reinterpret_cast<float2*>(C + (long long)r1*N + col) = v;
            }
        }
    }
}

// ---------------------------------------------------------------------------
// Per-head RMSNorm + RoPE for q and k; copy v. Block = 1 token, 256 threads.
// ---------------------------------------------------------------------------
__global__ __launch_bounds__(256) void qknorm_rope_kernel(
    const float* __restrict__ qkv,
    const float* __restrict__ qw, const float* __restrict__ kw,
    const int* __restrict__ positions,
    float* __restrict__ Qo, float* __restrict__ Ko, float* __restrict__ Vo)
{
    int t = blockIdx.x;
    int warp = threadIdx.x >> 5, lane = threadIdx.x & 31;
    float p = (float)positions[t];

    for (int vec = warp; vec < NH_ + NKV_; vec += 8) {
        bool isq = vec < NH_;
        const float* src = qkv + (long long)t*1536 + vec*HD_;
        float x0 = src[lane], x1 = src[lane + 32];
        float ss = x0*x0 + x1*x1;
        #pragma unroll
        for (int off = 16; off; off >>= 1) ss += __shfl_xor_sync(0xffffffffu, ss, off);
        float r = rsqrtf(ss / (float)HD_ + EPS_);
        const float* w = isq ? qw : kw;
        x0 = x0 * r * w[lane];
        x1 = x1 * r * w[lane + 32];
        int i = lane & 15;
        float inv = powf(10000.f, -((float)(2*i) / (float)ROT_));
        float ang = p * inv;
        float c = cosf(ang), s = sinf(ang);
        float partner = __shfl_xor_sync(0xffffffffu, x0, 16);
        float y0;
        if (lane < 16) y0 = x0 * c - partner * s;
        else           y0 = partner * s + x0 * c;
        x0 = y0;
        float* dst = isq ? (Qo + ((long long)t*NH_ + vec)*HD_)
                         : (Ko + ((long long)t*NKV_ + (vec - NH_))*HD_);
        dst[lane] = x0;
        dst[lane + 32] = x1;
    }
    for (int i = threadIdx.x; i < NKV_*HD_; i += blockDim.x)
        Vo[(long long)t*NKV_*HD_ + i] = qkv[(long long)t*1536 + 1280 + i];
}

// ---------------------------------------------------------------------------
// Flash attention (tensor cores). Br=64 queries/block, Bc=64 keys/tile.
// 4 warps; warp w owns query rows 16w..16w+15. S = Q K^T in 3xTF32 (fp32-level
// accuracy for softmax); P V in plain tf32. O fp32 accumulators.
// Fragment mappings identical to tf32gemm_kernel (empirically verified).
// smem: Ps (also Q staging) + Khi + Klo + Vs, each 64x68 floats.
// ---------------------------------------------------------------------------
#define ATT_LDR 68
#define ATT_SMEM_FLOATS (4*64*ATT_LDR)

__global__ __launch_bounds__(128) void flash_attn_kernel(
    const float* __restrict__ Q, const float* __restrict__ Kc,
    const float* __restrict__ Vc, float* __restrict__ O)
{
    extern __shared__ float sm[];
    float* Ps  = sm;                    // Q staging, then P tile
    float* Khi = sm + 64*ATT_LDR;
    float* Klo = sm + 2*64*ATT_LDR;
    float* Vs  = sm + 3*64*ATT_LDR;

    const int h = blockIdx.y;
    const int kvh = h >> 2;
    const int qb = ((int)gridDim.x - 1 - (int)blockIdx.x) * 64;  // reversed

    int tid = threadIdx.x, lane = tid & 31, warp = tid >> 5;
    int grp = lane >> 2, t4 = lane & 3;
    int wrow = warp * 16;

    // --- stage Q tile into Ps ---
    for (int idx = tid; idx < 64*16; idx += 128) {
        int r = idx >> 4, c = (idx & 15) * 4;
        float4 v = *(const float4*)&Q[((long long)(qb + r)*NH_ + h)*HD_ + c];
        Ps[r*ATT_LDR + c + 0] = v.x;
        Ps[r*ATT_LDR + c + 1] = v.y;
        Ps[r*ATT_LDR + c + 2] = v.z;
        Ps[r*ATT_LDR + c + 3] = v.w;
    }
    __syncthreads();

    // --- extract Q fragments (hi/lo), held in registers for all tiles ---
    uint32_t qh[8][4], ql[8][4];
    #pragma unroll
    for (int kc = 0; kc < 8; kc++) {
        int r0 = wrow + grp, r1 = wrow + grp + 8;
        int c0 = kc*8 + t4, c1 = c0 + 4;
        float x, hi;
        x = Ps[r0*ATT_LDR + c0]; hi = to_tf32(x);
        qh[kc][0] = __float_as_uint(hi); ql[kc][0] = tf32_bits(x - hi);
        x = Ps[r1*ATT_LDR + c0]; hi = to_tf32(x);
        qh[kc][1] = __float_as_uint(hi); ql[kc][1] = tf32_bits(x - hi);
        x = Ps[r0*ATT_LDR + c1]; hi = to_tf32(x);
        qh[kc][2] = __float_as_uint(hi); ql[kc][2] = tf32_bits(x - hi);
        x = Ps[r1*ATT_LDR + c1]; hi = to_tf32(x);
        qh[kc][3] = __float_as_uint(hi); ql[kc][3] = tf32_bits(x - hi);
    }

    float o[8][4];
    #pragma unroll
    for (int nt = 0; nt < 8; nt++)
        #pragma unroll
        for (int c = 0; c < 4; c++) o[nt][c] = 0.f;
    float m0 = -1e30f, m1 = -1e30f, l0 = 0.f, l1 = 0.f;

    const int nTiles = qb/64 + 1;
    for (int jt = 0; jt < nTiles; jt++) {
        int s0 = jt * 64;
        // --- load + convert K (hi/lo) and V (tf32) tiles ---
        for (int idx = tid; idx < 64*16; idx += 128) {
            int r = idx >> 4, c = (idx & 15) * 4;
            float4 kv = *(const float4*)&Kc[((long long)(s0 + r)*NKV_ + kvh)*HD_ + c];
            float h0 = to_tf32(kv.x), h1 = to_tf32(kv.y),
                  h2 = to_tf32(kv.z), h3 = to_tf32(kv.w);
            Khi[r*ATT_LDR + c + 0] = h0;  Klo[r*ATT_LDR + c + 0] = to_tf32(kv.x - h0);
            Khi[r*ATT_LDR + c + 1] = h1;  Klo[r*ATT_LDR + c + 1] = to_tf32(kv.y - h1);
            Khi[r*ATT_LDR + c + 2] = h2;  Klo[r*ATT_LDR + c + 2] = to_tf32(kv.z - h2);
            Khi[r*ATT_LDR + c + 3] = h3;  Klo[r*ATT_LDR + c + 3] = to_tf32(kv.w - h3);
            float4 vv = *(const float4*)&Vc[((long long)(s0 + r)*NKV_ + kvh)*HD_ + c];
            Vs[r*ATT_LDR + c + 0] = to_tf32(vv.x);
            Vs[r*ATT_LDR + c + 1] = to_tf32(vv.y);
            Vs[r*ATT_LDR + c + 2] = to_tf32(vv.z);
            Vs[r*ATT_LDR + c + 3] = to_tf32(vv.w);
        }
        __syncthreads();

        // --- S = Q K^T (3x tf32) ---
        float s[8][4];
        #pragma unroll
        for (int nt = 0; nt < 8; nt++)
            #pragma unroll
            for (int c = 0; c < 4; c++) s[nt][c] = 0.f;

        #pragma unroll
        for (int kc = 0; kc < 8; kc++) {
            #pragma unroll
            for (int nt = 0; nt < 8; nt++) {
                int srow = nt*8 + grp;
                uint32_t bh0 = __float_as_uint(Khi[srow*ATT_LDR + kc*8 + t4]);
                uint32_t bh1 = __float_as_uint(Khi[srow*ATT_LDR + kc*8 + t4 + 4]);
                uint32_t bl0 = __float_as_uint(Klo[srow*ATT_LDR + kc*8 + t4]);
                uint32_t bl1 = __float_as_uint(Klo[srow*ATT_LDR + kc*8 + t4 + 4]);
                MMA_TF32(s[nt][0], s[nt][1], s[nt][2], s[nt][3],
                         qh[kc][0], qh[kc][1], qh[kc][2], qh[kc][3], bh0, bh1);
                MMA_TF32(s[nt][0], s[nt][1], s[nt][2], s[nt][3],
                         qh[kc][0], qh[kc][1], qh[kc][2], qh[kc][3], bl0, bl1);
                MMA_TF32(s[nt][0], s[nt][1], s[nt][2], s[nt][3],
                         ql[kc][0], ql[kc][1], ql[kc][2], ql[kc][3], bh0, bh1);
            }
        }
        // scale
        #pragma unroll
        for (int nt = 0; nt < 8; nt++)
            #pragma unroll
            for (int c = 0; c < 4; c++) s[nt][c] *= 0.125f;

        // causal mask (diagonal tile only)
        if (s0 == qb) {
            int row0 = wrow + grp, row1 = wrow + grp + 8;
            #pragma unroll
            for (int nt = 0; nt < 8; nt++) {
                int col = nt*8 + 2*t4;
                if (col     > row0) s[nt][0] = -1e30f;
                if (col + 1 > row0) s[nt][1] = -1e30f;
                if (col     > row1) s[nt][2] = -1e30f;
                if (col + 1 > row1) s[nt][3] = -1e30f;
            }
        }

        // row maxima (2 rows per thread), reduce across quad (t4)
        float rmax0 = -1e30f, rmax1 = -1e30f;
        #pragma unroll
        for (int nt = 0; nt < 8; nt++) {
            rmax0 = fmaxf(rmax0, fmaxf(s[nt][0], s[nt][1]));
            rmax1 = fmaxf(rmax1, fmaxf(s[nt][2], s[nt][3]));
        }
        rmax0 = fmaxf(rmax0, __shfl_xor_sync(0xffffffffu, rmax0, 1));
        rmax0 = fmaxf(rmax0, __shfl_xor_sync(0xffffffffu, rmax0, 2));
        rmax1 = fmaxf(rmax1, __shfl_xor_sync(0xffffffffu, rmax1, 1));
        rmax1 = fmaxf(rmax1, __shfl_xor_sync(0xffffffffu, rmax1, 2));

        float mn0 = fmaxf(m0, rmax0), mn1 = fmaxf(m1, rmax1);
        float corr0 = __expf(m0 - mn0), corr1 = __expf(m1 - mn1);
        l0 *= corr0; l1 *= corr1;
        #pragma unroll
        for (int nt = 0; nt < 8; nt++) {
            o[nt][0] *= corr0; o[nt][1] *= corr0;
            o[nt][2] *= corr1; o[nt][3] *= corr1;
        }
        m0 = mn0; m1 = mn1;

        // P = exp(S - m), accumulate l, write P tile (own warp rows only)
        int prow0 = (wrow + grp) * ATT_LDR, prow1 = (wrow + grp + 8) * ATT_LDR;
        #pragma unroll
        for (int nt = 0; nt < 8; nt++) {
            int col = nt*8 + 2*t4;
            float p0 = __expf(s[nt][0] - mn0);
            float p1 = __expf(s[nt][1] - mn0);
            float p2 = __expf(s[nt][2] - mn1);
            float p3 = __expf(s[nt][3] - mn1);
            l0 += p0 + p1; l1 += p2 + p3;
            *(float2*)&Ps[prow0 + col] = make_float2(p0, p1);
            *(float2*)&Ps[prow1 + col] = make_float2(p2, p3);
        }
        __syncwarp();

        // --- O += P V (plain tf32) ---
        #pragma unroll
        for (int kc = 0; kc < 8; kc++) {
            uint32_t a0 = tf32_bits(Ps[prow0 + kc*8 + t4]);
            uint32_t a1 = tf32_bits(Ps[prow1 + kc*8 + t4]);
            uint32_t a2 = tf32_bits(Ps[prow0 + kc*8 + t4 + 4]);
            uint32_t a3 = tf32_bits(Ps[prow1 + kc*8 + t4 + 4]);
            #pragma unroll
            for (int nt = 0; nt < 8; nt++) {
                uint32_t b0 = __float_as_uint(Vs[(kc*8 + t4    )*ATT_LDR + nt*8 + grp]);
                uint32_t b1 = __float_as_uint(Vs[(kc*8 + t4 + 4)*ATT_LDR + nt*8 + grp]);
                MMA_TF32(o[nt][0], o[nt][1], o[nt][2], o[nt][3],
                         a0, a1, a2, a3, b0, b1);
            }
        }
        __syncthreads();   // protect K/V/P smem before next tile load
    }

    // final l across quad, normalize, store
    l0 += __shfl_xor_sync(0xffffffffu, l0, 1);
    l0 += __shfl_xor_sync(0xffffffffu, l0, 2);
    l1 += __shfl_xor_sync(0xffffffffu, l1, 1);
    l1 += __shfl_xor_sync(0xffffffffu, l1, 2);
    float inv0 = 1.f / l0, inv1 = 1.f / l1;
    int tg0 = qb + wrow + grp, tg1 = tg0 + 8;
    #pragma unroll
    for (int nt = 0; nt < 8; nt++) {
        int col = h*HD_ + nt*8 + 2*t4;
        *(float2*)&O[(long long)tg0*H_ + col] = make_float2(o[nt][0]*inv0, o[nt][1]*inv0);
        *(float2*)&O[(long long)tg1*H_ + col] = make_float2(o[nt][2]*inv1, o[nt][3]*inv1);
    }
}

// ---------------------------------------------------------------------------
// Router: warp per token. Exact replication of group top-k routing (fp32).
// ---------------------------------------------------------------------------
__global__ __launch_bounds__(128) void router_kernel(
    const float* __restrict__ h2, const float* __restrict__ Wg,
    const float* __restrict__ bias, int* __restrict__ ids,
    float* __restrict__ wout)
{
    int warp = threadIdx.x >> 5, lane = threadIdx.x & 31;
    int t = blockIdx.x * 4 + warp;
    const float* h = h2 + (long long)t * H_;
    float acc = 0.f;
    for (int k = 0; k < H_; k++) acc += __ldg(&h[k]) * __ldg(&Wg[k*E_ + lane]);
    float scr = 1.f / (1.f + expf(-acc));
    __shared__ float s_scr[4][E_];
    __shared__ float s_sfc[4][E_];
    s_scr[warp][lane] = scr;
    s_sfc[warp][lane] = scr + bias[lane];
    __syncwarp();
    if (lane == 0) {
        float* sc = s_scr[warp];
        float* sf = s_sfc[warp];
        float gs[NG_];
        for (int g = 0; g < NG_; g++) {
            float m1 = -1e30f, m2 = -1e30f;
            for (int j = 0; j < E_/NG_; j++) {
                float v = sf[g*(E_/NG_) + j];
                if (v > m1) { m2 = m1; m1 = v; }
                else if (v > m2) { m2 = v; }
            }
            gs[g] = m1 + m2;
        }
        int g1 = 0;
        for (int g = 1; g < NG_; g++) if (gs[g] > gs[g1]) g1 = g;
        int g2 = -1;
        for (int g = 0; g < NG_; g++) {
            if (g == g1) continue;
            if (g2 < 0 || gs[g] > gs[g2]) g2 = g;
        }
        bool used[E_];
        for (int e = 0; e < E_; e++) used[e] = false;
        int sel[TOPK_];
        for (int kk = 0; kk < TOPK_; kk++) {
            int best = -1; float bv = -1e30f;
            for (int e = 0; e < E_; e++) {
                int g = e >> 3;
                if ((g != g1 && g != g2) || used[e]) continue;
                if (sf[e] > bv) { bv = sf[e]; best = e; }
            }
            used[best] = true;
            sel[kk] = best;
        }
        float wsum = 0.f, wv[TOPK_];
        for (int kk = 0; kk < TOPK_; kk++) { wv[kk] = sc[sel[kk]]; wsum += wv[kk]; }
        for (int kk = 0; kk < TOPK_; kk++) {
            ids[t*TOPK_ + kk]  = sel[kk];
            wout[t*TOPK_ + kk] = wv[kk] / wsum;
        }
    }
}

// ---------------------------------------------------------------------------
// Counting sort of (token,slot) by expert. Single block.
// ---------------------------------------------------------------------------
__global__ __launch_bounds__(256) void sort_kernel(
    const int* __restrict__ ids, int* __restrict__ sorted_token,
    int* __restrict__ slotpos, int* __restrict__ offs)
{
    __shared__ int cnt[E_], start[E_];
    int tid = threadIdx.x;
    if (tid < E_) cnt[tid] = 0;
    __syncthreads();
    for (int i = tid; i < T_*TOPK_; i += blockDim.x) atomicAdd(&cnt[ids[i]], 1);
    __syncthreads();
    if (tid == 0) {
        int acc = 0;
        for (int e = 0; e < E_; e++) { offs[e] = acc; start[e] = acc; acc += cnt[e]; }
        offs[E_] = acc;
    }
    __syncthreads();
    for (int i = tid; i < T_*TOPK_; i += blockDim.x) {
        int e = ids[i];
        int pos = atomicAdd(&start[e], 1);
        sorted_token[pos] = i >> 2;
        slotpos[i] = pos;
    }
}

// ---------------------------------------------------------------------------
// act = silu(gu[:, :IM]) * gu[:, IM:]
// ---------------------------------------------------------------------------
__global__ __launch_bounds__(256) void silu_mul_kernel(
    const float* __restrict__ gu, float* __restrict__ out, int rows, int im)
{
    long long idx = (long long)blockIdx.x * blockDim.x + threadIdx.x;
    long long total = (long long)rows * im;
    if (idx >= total) return;
    long long r = idx / im;
    int j = (int)(idx - r * im);
    float a = gu[r*(2*im) + j];
    float b = gu[r*(2*im) + im + j];
    float s = a / (1.f + __expf(-a));
    out[idx] = s * b;
}

// ---------------------------------------------------------------------------
// out[t] = shared[t] + sum_k w[t,k] * slot_out[slotpos[t,k]]
// ---------------------------------------------------------------------------
__global__ __launch_bounds__(256) void combine_kernel(
    const float* __restrict__ shexp, const float* __restrict__ slot_out,
    const int* __restrict__ slotpos, const float* __restrict__ w,
    float* __restrict__ out)
{
    int t = blockIdx.x;
    int i = threadIdx.x;
    int p[TOPK_]; float wv[TOPK_];
    #pragma unroll
    for (int k = 0; k < TOPK_; k++) { p[k] = slotpos[t*TOPK_+k]; wv[k] = w[t*TOPK_+k]; }
    float4 acc = ((const float4*)(shexp + (long long)t*H_))[i];
    #pragma unroll
    for (int k = 0; k < TOPK_; k++) {
        float4 v = ((const float4*)(slot_out + (long long)p[k]*H_))[i];
        acc.x += wv[k]*v.x; acc.y += wv[k]*v.y; acc.z += wv[k]*v.z; acc.w += wv[k]*v.w;
    }
    ((float4*)(out + (long long)t*H_))[i] = acc;
}

// ---------------------------------------------------------------------------
// Launch
// ---------------------------------------------------------------------------
extern "C" void kernel_launch(void* const* d_in, const int* in_sizes, int n_in,
                              void* d_out, int out_size)
{
    const float* hidden    = (const float*)d_in[0];
    const float* residual  = (const float*)d_in[1];
    const float* in_ln_w   = (const float*)d_in[2];
    const float* post_ln_w = (const float*)d_in[3];
    const float* q_norm_w  = (const float*)d_in[4];
    const float* k_norm_w  = (const float*)d_in[5];
    const float* Wqkv      = (const float*)d_in[6];
    const float* Wo        = (const float*)d_in[7];
    const float* Wg        = (const float*)d_in[8];
    const float* gate_bias = (const float*)d_in[9];
    const float* Wgu       = (const float*)d_in[10];
    const float* Wd        = (const float*)d_in[11];
    const float* Wgu_sh    = (const float*)d_in[12];
    const float* Wd_sh     = (const float*)d_in[13];
    const int*   positions = (const int*)d_in[14];

    float* out_hidden = (float*)d_out;
    float* out_resid  = out_hidden + (size_t)T_ * H_;

    float *p_r1, *p_ln1, *p_qkv, *p_q, *p_k, *p_v, *p_att, *p_h2;
    float *p_w, *p_gu, *p_act, *p_slot, *p_gus, *p_actsh, *p_shared;
    int *p_ids, *p_sorted, *p_slotpos, *p_offs;
    cudaGetSymbolAddress((void**)&p_r1,      g_r1);
    cudaGetSymbolAddress((void**)&p_ln1,     g_ln1);
    cudaGetSymbolAddress((void**)&p_qkv,     g_qkv);
    cudaGetSymbolAddress((void**)&p_q,       g_q);
    cudaGetSymbolAddress((void**)&p_k,       g_k);
    cudaGetSymbolAddress((void**)&p_v,       g_v);
    cudaGetSymbolAddress((void**)&p_att,     g_att);
    cudaGetSymbolAddress((void**)&p_h2,      g_h2);
    cudaGetSymbolAddress((void**)&p_w,       g_w);
    cudaGetSymbolAddress((void**)&p_ids,     g_ids);
    cudaGetSymbolAddress((void**)&p_sorted,  g_sorted);
    cudaGetSymbolAddress((void**)&p_slotpos, g_slotpos);
    cudaGetSymbolAddress((void**)&p_offs,    g_offs);
    cudaGetSymbolAddress((void**)&p_gu,      g_gu);
    cudaGetSymbolAddress((void**)&p_act,     g_actbuf);
    cudaGetSymbolAddress((void**)&p_slot,    g_slot);
    cudaGetSymbolAddress((void**)&p_gus,     g_gus);
    cudaGetSymbolAddress((void**)&p_actsh,   g_actsh);
    cudaGetSymbolAddress((void**)&p_shared,  g_shared);

    // Idempotent, unconditional (no static guards — harness rule), not a
    // stream op so legal under graph capture.
    cudaFuncSetAttribute(flash_attn_kernel,
                         cudaFuncAttributeMaxDynamicSharedMemorySize,
                         ATT_SMEM_FLOATS * (int)sizeof(float));

    // 1) r1 = hidden + residual ; ln1 = rms(r1)*in_ln_w
    add_rms_kernel<<<T_, 256>>>(hidden, residual, in_ln_w, p_r1, p_ln1);

    // 2) qkv = ln1 @ Wqkv  (fp32: routing-critical)
    sgemm_kernel<false><<<dim3(1536/128, T_/128), 256>>>(
        p_ln1, Wqkv, p_qkv, nullptr, T_, 1536, H_);

    // 3) per-head rms + rope
    qknorm_rope_kernel<<<T_, 256>>>(p_qkv, q_norm_w, k_norm_w, positions,
                                    p_q, p_k, p_v);

    // 4) attention (flash, 3xTF32 scores + tf32 PV)
    flash_attn_kernel<<<dim3(T_/64, NH_), 128,
                        ATT_SMEM_FLOATS * sizeof(float)>>>(p_q, p_k, p_v, p_att);

    // 5) r2 = att @ Wo + r1  -> out_resid (fp32: routing-critical)
    sgemm_kernel<true><<<dim3(H_/128, T_/128), 256>>>(
        p_att, Wo, out_resid, p_r1, T_, H_, H_);

    // 6) h2 = rms(r2)*post_ln_w
    add_rms_kernel<<<T_, 256>>>(out_resid, nullptr, post_ln_w, nullptr, p_h2);

    // 7) router (fp32 exact)
    router_kernel<<<T_/4, 128>>>(p_h2, Wg, gate_bias, p_ids, p_w);

    // 8) counting sort by expert
    sort_kernel<<<1, 256>>>(p_ids, p_sorted, p_slotpos, p_offs);

    // 9) routed up-proj (tf32 TC, gathered+segmented)
    tf32gemm_kernel<true,true><<<dim3(2*IM_/128, 64, E_), 256>>>(
        p_h2, Wgu, p_gu, 0, 2*IM_, H_, p_sorted, p_offs,
        (long long)H_ * 2*IM_);

    // 10) silu-mul for routed
    silu_mul_kernel<<<(T_*TOPK_*IM_ + 255)/256, 256>>>(p_gu, p_act, T_*TOPK_, IM_);

    // 11) routed down-proj (tf32 TC, segmented)
    tf32gemm_kernel<true,false><<<dim3(H_/128, 64, E_), 256>>>(
        p_act, Wd, p_slot, 0, H_, IM_, nullptr, p_offs,
        (long long)IM_ * H_);

    // 12) shared expert up (tf32 TC)
    tf32gemm_kernel<false,false><<<dim3(2*ISH_/128, T_/128), 256>>>(
        p_h2, Wgu_sh, p_gus, T_, 2*ISH_, H_, nullptr, nullptr, 0);

    // 13) silu-mul shared
    silu_mul_kernel<<<(T_*ISH_ + 255)/256, 256>>>(p_gus, p_actsh, T_, ISH_);

    // 14) shared expert down (tf32 TC)
    tf32gemm_kernel<false,false><<<dim3(H_/128, T_/128), 256>>>(
        p_actsh, Wd_sh, p_shared, T_, H_, ISH_, nullptr, nullptr, 0);

    // 15) out_hidden = shared + sum_k w_k * slot_out
    combine_kernel<<<T_, 256>>>(p_shared, p_slot, p_slotpos, p_w, out_hidden);
}

// round 7
// speedup vs baseline: 2.2417x; 1.0250x over previous
#include <cuda_runtime.h>
#include <cuda_bf16.h>
#include <math.h>
#include <stdint.h>

// ---------------------------------------------------------------------------
// Problem constants
// ---------------------------------------------------------------------------
#define T_   2048
#define H_   1024
#define NH_  16
#define NKV_ 4
#define HD_  64
#define E_   32
#define TOPK_ 4
#define NG_  4
#define TG_  2
#define IM_  384
#define ISH_ 384
#define ROT_ 32      // HD/2
#define EPS_ 1e-5f

// ---------------------------------------------------------------------------
// Scratch (device globals — allocation-free per harness rules)
// ---------------------------------------------------------------------------
__device__ float g_r1     [T_*H_];
__device__ float g_ln1    [T_*H_];
__device__ float g_qkv    [T_*1536];
__device__ float g_q      [T_*NH_*HD_];
__device__ float g_k      [T_*NKV_*HD_];
__device__ float g_v      [T_*NKV_*HD_];
__device__ float g_att    [T_*H_];
__device__ float g_h2     [T_*H_];
__device__ float g_w      [T_*TOPK_];
__device__ int   g_ids    [T_*TOPK_];
__device__ int   g_sorted [T_*TOPK_];
__device__ int   g_slotpos[T_*TOPK_];
__device__ int   g_offs   [E_+1];
__device__ float g_gu     [T_*TOPK_*2*IM_];
__device__ float g_actbuf [T_*TOPK_*IM_];
__device__ float g_slot   [T_*TOPK_*H_];
__device__ float g_gus    [T_*2*ISH_];
__device__ float g_actsh  [T_*ISH_];
__device__ float g_shared [T_*H_];

// ---------------------------------------------------------------------------
// Helpers
// ---------------------------------------------------------------------------
__device__ __forceinline__ float to_tf32(float x) {
    uint32_t u;
    asm("cvt.rna.tf32.f32 %0, %1;" : "=r"(u) : "f"(x));
    return __uint_as_float(u);
}
__device__ __forceinline__ uint32_t tf32_bits(float x) {
    uint32_t u;
    asm("cvt.rna.tf32.f32 %0, %1;" : "=r"(u) : "f"(x));
    return u;
}

#define MMA_TF32(d0,d1,d2,d3,a0,a1,a2,a3,b0,b1)                               \
    asm volatile(                                                             \
        "mma.sync.aligned.m16n8k8.row.col.f32.tf32.tf32.f32 "                 \
        "{%0,%1,%2,%3},{%4,%5,%6,%7},{%8,%9},{%0,%1,%2,%3};"                  \
        : "+f"(d0), "+f"(d1), "+f"(d2), "+f"(d3)                              \
        : "r"(a0), "r"(a1), "r"(a2), "r"(a3), "r"(b0), "r"(b1))

// ---------------------------------------------------------------------------
// add + RMSNorm (row per block, 256 threads, float4). b / resid optional.
// ---------------------------------------------------------------------------
__global__ __launch_bounds__(256) void add_rms_kernel(
    const float* __restrict__ a, const float* __restrict__ b,
    const float* __restrict__ w, float* __restrict__ resid,
    float* __restrict__ out)
{
    int t = blockIdx.x;
    int i = threadIdx.x;
    float4 va = ((const float4*)(a + (long long)t*H_))[i];
    if (b) {
        float4 vb = ((const float4*)(b + (long long)t*H_))[i];
        va.x += vb.x; va.y += vb.y; va.z += vb.z; va.w += vb.w;
    }
    if (resid) ((float4*)(resid + (long long)t*H_))[i] = va;
    float ss = va.x*va.x + va.y*va.y + va.z*va.z + va.w*va.w;
    __shared__ float sred[8];
    #pragma unroll
    for (int off = 16; off; off >>= 1) ss += __shfl_xor_sync(0xffffffffu, ss, off);
    if ((i & 31) == 0) sred[i >> 5] = ss;
    __syncthreads();
    if (i < 8) {
        float v = sred[i];
        #pragma unroll
        for (int off = 4; off; off >>= 1) v += __shfl_xor_sync(0xffu, v, off);
        if (i == 0) sred[0] = v;
    }
    __syncthreads();
    float rs = rsqrtf(sred[0] / (float)H_ + EPS_);
    float4 vw = ((const float4*)w)[i];
    va.x *= rs * vw.x; va.y *= rs * vw.y; va.z *= rs * vw.z; va.w *= rs * vw.w;
    ((float4*)(out + (long long)t*H_))[i] = va;
}

// ---------------------------------------------------------------------------
// 3xTF32 tensor-core GEMM (fp32-class accuracy), 128x128x16 tile, 256 thr.
// Used for routing-critical GEMMs (QKV, O-proj). ADD: C = A@B + addsrc.
// M, N, K must be multiples of 128/128/16 (true at both call sites).
// ---------------------------------------------------------------------------
template<bool ADD>
__global__ __launch_bounds__(256) void tf32gemm3x_kernel(
    const float* __restrict__ A, const float* __restrict__ B,
    float* __restrict__ C, const float* __restrict__ addsrc,
    int M, int N, int K)
{
    constexpr int BK = 16;
    __shared__ float Ah[128][BK + 4], Al[128][BK + 4];
    __shared__ float Bh[BK][128 + 8], Bl[BK][128 + 8];

    int row0 = blockIdx.y * 128;
    int col0 = blockIdx.x * 128;

    int tid = threadIdx.x, lane = tid & 31, warp = tid >> 5;
    int grp = lane >> 2, t4 = lane & 3;
    int wm = (warp >> 2) * 64;
    int wn = (warp & 3) * 32;

    int ar = tid >> 2, av = tid & 3;
    int bk = tid >> 4, bn = tid & 15;

    float acc[4][4][4];
    #pragma unroll
    for (int mt = 0; mt < 4; mt++)
        #pragma unroll
        for (int nt = 0; nt < 4; nt++)
            #pragma unroll
            for (int c = 0; c < 4; c++) acc[mt][nt][c] = 0.f;

    for (int k0 = 0; k0 < K; k0 += BK) {
        float4 a0 = *reinterpret_cast<const float4*>(
            A + (long long)(row0 + ar) * K + k0 + av*4);
        float4 a1 = *reinterpret_cast<const float4*>(
            A + (long long)(row0 + ar + 64) * K + k0 + av*4);
        {
            float h;
            h = to_tf32(a0.x); Ah[ar][av*4+0] = h; Al[ar][av*4+0] = to_tf32(a0.x - h);
            h = to_tf32(a0.y); Ah[ar][av*4+1] = h; Al[ar][av*4+1] = to_tf32(a0.y - h);
            h = to_tf32(a0.z); Ah[ar][av*4+2] = h; Al[ar][av*4+2] = to_tf32(a0.z - h);
            h = to_tf32(a0.w); Ah[ar][av*4+3] = h; Al[ar][av*4+3] = to_tf32(a0.w - h);
            h = to_tf32(a1.x); Ah[ar+64][av*4+0] = h; Al[ar+64][av*4+0] = to_tf32(a1.x - h);
            h = to_tf32(a1.y); Ah[ar+64][av*4+1] = h; Al[ar+64][av*4+1] = to_tf32(a1.y - h);
            h = to_tf32(a1.z); Ah[ar+64][av*4+2] = h; Al[ar+64][av*4+2] = to_tf32(a1.z - h);
            h = to_tf32(a1.w); Ah[ar+64][av*4+3] = h; Al[ar+64][av*4+3] = to_tf32(a1.w - h);
        }
        float4 b0 = *reinterpret_cast<const float4*>(
            B + (long long)(k0 + bk) * N + col0 + bn*4);
        float4 b1 = *reinterpret_cast<const float4*>(
            B + (long long)(k0 + bk) * N + col0 + bn*4 + 64);
        {
            float h;
            h = to_tf32(b0.x); Bh[bk][bn*4+0]  = h; Bl[bk][bn*4+0]  = to_tf32(b0.x - h);
            h = to_tf32(b0.y); Bh[bk][bn*4+1]  = h; Bl[bk][bn*4+1]  = to_tf32(b0.y - h);
            h = to_tf32(b0.z); Bh[bk][bn*4+2]  = h; Bl[bk][bn*4+2]  = to_tf32(b0.z - h);
            h = to_tf32(b0.w); Bh[bk][bn*4+3]  = h; Bl[bk][bn*4+3]  = to_tf32(b0.w - h);
            h = to_tf32(b1.x); Bh[bk][bn*4+64] = h; Bl[bk][bn*4+64] = to_tf32(b1.x - h);
            h = to_tf32(b1.y); Bh[bk][bn*4+65] = h; Bl[bk][bn*4+65] = to_tf32(b1.y - h);
            h = to_tf32(b1.z); Bh[bk][bn*4+66] = h; Bl[bk][bn*4+66] = to_tf32(b1.z - h);
            h = to_tf32(b1.w); Bh[bk][bn*4+67] = h; Bl[bk][bn*4+67] = to_tf32(b1.w - h);
        }
        __syncthreads();

        #pragma unroll
        for (int ks = 0; ks < 2; ks++) {
            uint32_t ah[4][4], al[4][4];
            #pragma unroll
            for (int mt = 0; mt < 4; mt++) {
                int r = wm + mt*16;
                ah[mt][0] = __float_as_uint(Ah[r+grp  ][ks*8 + t4    ]);
                ah[mt][1] = __float_as_uint(Ah[r+grp+8][ks*8 + t4    ]);
                ah[mt][2] = __float_as_uint(Ah[r+grp  ][ks*8 + t4 + 4]);
                ah[mt][3] = __float_as_uint(Ah[r+grp+8][ks*8 + t4 + 4]);
                al[mt][0] = __float_as_uint(Al[r+grp  ][ks*8 + t4    ]);
                al[mt][1] = __float_as_uint(Al[r+grp+8][ks*8 + t4    ]);
                al[mt][2] = __float_as_uint(Al[r+grp  ][ks*8 + t4 + 4]);
                al[mt][3] = __float_as_uint(Al[r+grp+8][ks*8 + t4 + 4]);
            }
            uint32_t bh[4][2], bl[4][2];
            #pragma unroll
            for (int nt = 0; nt < 4; nt++) {
                bh[nt][0] = __float_as_uint(Bh[ks*8 + t4    ][wn + nt*8 + grp]);
                bh[nt][1] = __float_as_uint(Bh[ks*8 + t4 + 4][wn + nt*8 + grp]);
                bl[nt][0] = __float_as_uint(Bl[ks*8 + t4    ][wn + nt*8 + grp]);
                bl[nt][1] = __float_as_uint(Bl[ks*8 + t4 + 4][wn + nt*8 + grp]);
            }
            #pragma unroll
            for (int mt = 0; mt < 4; mt++)
                #pragma unroll
                for (int nt = 0; nt < 4; nt++) {
                    MMA_TF32(acc[mt][nt][0], acc[mt][nt][1],
                             acc[mt][nt][2], acc[mt][nt][3],
                             ah[mt][0], ah[mt][1], ah[mt][2], ah[mt][3],
                             bh[nt][0], bh[nt][1]);
                    MMA_TF32(acc[mt][nt][0], acc[mt][nt][1],
                             acc[mt][nt][2], acc[mt][nt][3],
                             ah[mt][0], ah[mt][1], ah[mt][2], ah[mt][3],
                             bl[nt][0], bl[nt][1]);
                    MMA_TF32(acc[mt][nt][0], acc[mt][nt][1],
                             acc[mt][nt][2], acc[mt][nt][3],
                             al[mt][0], al[mt][1], al[mt][2], al[mt][3],
                             bh[nt][0], bh[nt][1]);
                }
        }
        __syncthreads();
    }

    #pragma unroll
    for (int mt = 0; mt < 4; mt++) {
        int r0 = row0 + wm + mt*16 + grp;
        int r1 = r0 + 8;
        #pragma unroll
        for (int nt = 0; nt < 4; nt++) {
            int col = col0 + wn + nt*8 + 2*t4;
            float2 v0 = make_float2(acc[mt][nt][0], acc[mt][nt][1]);
            float2 v1 = make_float2(acc[mt][nt][2], acc[mt][nt][3]);
            if (ADD) {
                float2 a0 = *reinterpret_cast<const float2*>(
                    addsrc + (long long)r0*N + col);
                float2 a1 = *reinterpret_cast<const float2*>(
                    addsrc + (long long)r1*N + col);
                v0.x += a0.x; v0.y += a0.y;
                v1.x += a1.x; v1.y += a1.y;
            }
            *reinterpret_cast<float2*>(C + (long long)r0*N + col) = v0;
            *reinterpret_cast<float2*>(C + (long long)r1*N + col) = v1;
        }
    }
}

// ---------------------------------------------------------------------------
// tf32 tensor-core GEMM (mma.sync m16n8k8), 128x128x16 tile, 256 threads.
// MoE GEMMs only (downstream of routing).
// ---------------------------------------------------------------------------
template<bool SEG, bool GATHER>
__global__ __launch_bounds__(256) void tf32gemm_kernel(
    const float* __restrict__ A, const float* __restrict__ Bbase,
    float* __restrict__ C, int M, int N, int K,
    const int* __restrict__ gather, const int* __restrict__ segoffs,
    long long bStride)
{
    constexpr int BM = 128, BN = 128, BK = 16;
    __shared__ float As[BM][BK + 4];
    __shared__ float Bs[BK][BN + 8];

    int rowBeg, rowEnd, z = 0;
    if (SEG) {
        z = blockIdx.z;
        rowBeg = segoffs[z];
        rowEnd = segoffs[z+1];
    } else {
        rowBeg = 0;
        rowEnd = M;
    }
    int row0 = rowBeg + blockIdx.y * BM;
    if (row0 >= rowEnd) return;
    int col0 = blockIdx.x * BN;
    const float* B = SEG ? (Bbase + (long long)z * bStride) : Bbase;

    int tid = threadIdx.x, lane = tid & 31, warp = tid >> 5;
    int grp = lane >> 2, t4 = lane & 3;
    int wm = (warp >> 2) * 64;
    int wn = (warp & 3) * 32;

    int ar = tid >> 2, av = tid & 3;
    int r0g = row0 + ar, r1g = row0 + ar + 64;
    bool v0 = r0g < rowEnd, v1 = r1g < rowEnd;
    long long sr0 = GATHER ? (v0 ? gather[r0g] : 0) : (v0 ? (long long)r0g : 0);
    long long sr1 = GATHER ? (v1 ? gather[r1g] : 0) : (v1 ? (long long)r1g : 0);
    int bk = tid >> 4, bn = tid & 15;

    float acc[4][4][4];
    #pragma unroll
    for (int mt = 0; mt < 4; mt++)
        #pragma unroll
        for (int nt = 0; nt < 4; nt++)
            #pragma unroll
            for (int c = 0; c < 4; c++) acc[mt][nt][c] = 0.f;

    for (int k0 = 0; k0 < K; k0 += BK) {
        float4 a0 = make_float4(0.f,0.f,0.f,0.f), a1 = a0;
        if (v0) a0 = *reinterpret_cast<const float4*>(A + sr0*K + k0 + av*4);
        if (v1) a1 = *reinterpret_cast<const float4*>(A + sr1*K + k0 + av*4);
        As[ar   ][av*4+0] = to_tf32(a0.x);
        As[ar   ][av*4+1] = to_tf32(a0.y);
        As[ar   ][av*4+2] = to_tf32(a0.z);
        As[ar   ][av*4+3] = to_tf32(a0.w);
        As[ar+64][av*4+0] = to_tf32(a1.x);
        As[ar+64][av*4+1] = to_tf32(a1.y);
        As[ar+64][av*4+2] = to_tf32(a1.z);
        As[ar+64][av*4+3] = to_tf32(a1.w);

        float4 b0 = *reinterpret_cast<const float4*>(
            B + (long long)(k0 + bk) * N + col0 + bn*4);
        float4 b1 = *reinterpret_cast<const float4*>(
            B + (long long)(k0 + bk) * N + col0 + bn*4 + 64);
        Bs[bk][bn*4+0]  = to_tf32(b0.x);
        Bs[bk][bn*4+1]  = to_tf32(b0.y);
        Bs[bk][bn*4+2]  = to_tf32(b0.z);
        Bs[bk][bn*4+3]  = to_tf32(b0.w);
        Bs[bk][bn*4+64] = to_tf32(b1.x);
        Bs[bk][bn*4+65] = to_tf32(b1.y);
        Bs[bk][bn*4+66] = to_tf32(b1.z);
        Bs[bk][bn*4+67] = to_tf32(b1.w);
        __syncthreads();

        #pragma unroll
        for (int ks = 0; ks < 2; ks++) {
            uint32_t af[4][4];
            #pragma unroll
            for (int mt = 0; mt < 4; mt++) {
                int r = wm + mt*16;
                af[mt][0] = __float_as_uint(As[r+grp  ][ks*8 + t4    ]);
                af[mt][1] = __float_as_uint(As[r+grp+8][ks*8 + t4    ]);
                af[mt][2] = __float_as_uint(As[r+grp  ][ks*8 + t4 + 4]);
                af[mt][3] = __float_as_uint(As[r+grp+8][ks*8 + t4 + 4]);
            }
            uint32_t bf[4][2];
            #pragma unroll
            for (int nt = 0; nt < 4; nt++) {
                bf[nt][0] = __float_as_uint(Bs[ks*8 + t4    ][wn + nt*8 + grp]);
                bf[nt][1] = __float_as_uint(Bs[ks*8 + t4 + 4][wn + nt*8 + grp]);
            }
            #pragma unroll
            for (int mt = 0; mt < 4; mt++)
                #pragma unroll
                for (int nt = 0; nt < 4; nt++)
                    MMA_TF32(acc[mt][nt][0], acc[mt][nt][1],
                             acc[mt][nt][2], acc[mt][nt][3],
                             af[mt][0], af[mt][1], af[mt][2], af[mt][3],
                             bf[nt][0], bf[nt][1]);
        }
        __syncthreads();
    }

    #pragma unroll
    for (int mt = 0; mt < 4; mt++) {
        int r0 = row0 + wm + mt*16 + grp;
        int r1 = r0 + 8;
        #pragma unroll
        for (int nt = 0; nt < 4; nt++) {
            int col = col0 + wn + nt*8 + 2*t4;
            if (r0 < rowEnd) {
                float2 v = make_float2(acc[mt][nt][0], acc[mt][nt][1]);
                *reinterpret_cast<float2*>(C + (long long)r0*N + col) = v;
            }
            if (r1 < rowEnd) {
                float2 v = make_float2(acc[mt][nt][2], acc[mt][nt][3]);
                *reinterpret_cast<float2*>(C + (long long)r1*N + col) = v;
            }
        }
    }
}

// ---------------------------------------------------------------------------
// Per-head RMSNorm + RoPE for q and k; copy v. Block = 1 token, 256 threads.
// ---------------------------------------------------------------------------
__global__ __launch_bounds__(256) void qknorm_rope_kernel(
    const float* __restrict__ qkv,
    const float* __restrict__ qw, const float* __restrict__ kw,
    const int* __restrict__ positions,
    float* __restrict__ Qo, float* __restrict__ Ko, float* __restrict__ Vo)
{
    int t = blockIdx.x;
    int warp = threadIdx.x >> 5, lane = threadIdx.x & 31;
    float p = (float)positions[t];

    for (int vec = warp; vec < NH_ + NKV_; vec += 8) {
        bool isq = vec < NH_;
        const float* src = qkv + (long long)t*1536 + vec*HD_;
        float x0 = src[lane], x1 = src[lane + 32];
        float ss = x0*x0 + x1*x1;
        #pragma unroll
        for (int off = 16; off; off >>= 1) ss += __shfl_xor_sync(0xffffffffu, ss, off);
        float r = rsqrtf(ss / (float)HD_ + EPS_);
        const float* w = isq ? qw : kw;
        x0 = x0 * r * w[lane];
        x1 = x1 * r * w[lane + 32];
        int i = lane & 15;
        float inv = powf(10000.f, -((float)(2*i) / (float)ROT_));
        float ang = p * inv;
        float c = cosf(ang), s = sinf(ang);
        float partner = __shfl_xor_sync(0xffffffffu, x0, 16);
        float y0;
        if (lane < 16) y0 = x0 * c - partner * s;
        else           y0 = partner * s + x0 * c;
        x0 = y0;
        float* dst = isq ? (Qo + ((long long)t*NH_ + vec)*HD_)
                         : (Ko + ((long long)t*NKV_ + (vec - NH_))*HD_);
        dst[lane] = x0;
        dst[lane + 32] = x1;
    }
    for (int i = threadIdx.x; i < NKV_*HD_; i += blockDim.x)
        Vo[(long long)t*NKV_*HD_ + i] = qkv[(long long)t*1536 + 1280 + i];
}

// ---------------------------------------------------------------------------
// Flash attention (tensor cores). Br=64 queries/block, Bc=64 keys/tile.
// 4 warps. S = Q K^T in 3xTF32; P V in plain tf32. O fp32 accumulators.
// ---------------------------------------------------------------------------
#define ATT_LDR 68
#define ATT_SMEM_FLOATS (4*64*ATT_LDR)

__global__ __launch_bounds__(128) void flash_attn_kernel(
    const float* __restrict__ Q, const float* __restrict__ Kc,
    const float* __restrict__ Vc, float* __restrict__ O)
{
    extern __shared__ float sm[];
    float* Ps  = sm;                    // Q staging, then P tile
    float* Khi = sm + 64*ATT_LDR;
    float* Klo = sm + 2*64*ATT_LDR;
    float* Vs  = sm + 3*64*ATT_LDR;

    const int h = blockIdx.y;
    const int kvh = h >> 2;
    const int qb = ((int)gridDim.x - 1 - (int)blockIdx.x) * 64;  // reversed

    int tid = threadIdx.x, lane = tid & 31, warp = tid >> 5;
    int grp = lane >> 2, t4 = lane & 3;
    int wrow = warp * 16;

    // --- stage Q tile into Ps ---
    for (int idx = tid; idx < 64*16; idx += 128) {
        int r = idx >> 4, c = (idx & 15) * 4;
        float4 v = *(const float4*)&Q[((long long)(qb + r)*NH_ + h)*HD_ + c];
        Ps[r*ATT_LDR + c + 0] = v.x;
        Ps[r*ATT_LDR + c + 1] = v.y;
        Ps[r*ATT_LDR + c + 2] = v.z;
        Ps[r*ATT_LDR + c + 3] = v.w;
    }
    __syncthreads();

    // --- extract Q fragments (hi/lo), held in registers for all tiles ---
    uint32_t qh[8][4], ql[8][4];
    #pragma unroll
    for (int kc = 0; kc < 8; kc++) {
        int r0 = wrow + grp, r1 = wrow + grp + 8;
        int c0 = kc*8 + t4, c1 = c0 + 4;
        float x, hi;
        x = Ps[r0*ATT_LDR + c0]; hi = to_tf32(x);
        qh[kc][0] = __float_as_uint(hi); ql[kc][0] = tf32_bits(x - hi);
        x = Ps[r1*ATT_LDR + c0]; hi = to_tf32(x);
        qh[kc][1] = __float_as_uint(hi); ql[kc][1] = tf32_bits(x - hi);
        x = Ps[r0*ATT_LDR + c1]; hi = to_tf32(x);
        qh[kc][2] = __float_as_uint(hi); ql[kc][2] = tf32_bits(x - hi);
        x = Ps[r1*ATT_LDR + c1]; hi = to_tf32(x);
        qh[kc][3] = __float_as_uint(hi); ql[kc][3] = tf32_bits(x - hi);
    }

    float o[8][4];
    #pragma unroll
    for (int nt = 0; nt < 8; nt++)
        #pragma unroll
        for (int c = 0; c < 4; c++) o[nt][c] = 0.f;
    float m0 = -1e30f, m1 = -1e30f, l0 = 0.f, l1 = 0.f;

    const int nTiles = qb/64 + 1;
    for (int jt = 0; jt < nTiles; jt++) {
        int s0 = jt * 64;
        for (int idx = tid; idx < 64*16; idx += 128) {
            int r = idx >> 4, c = (idx & 15) * 4;
            float4 kv = *(const float4*)&Kc[((long long)(s0 + r)*NKV_ + kvh)*HD_ + c];
            float h0 = to_tf32(kv.x), h1 = to_tf32(kv.y),
                  h2 = to_tf32(kv.z), h3 = to_tf32(kv.w);
            Khi[r*ATT_LDR + c + 0] = h0;  Klo[r*ATT_LDR + c + 0] = to_tf32(kv.x - h0);
            Khi[r*ATT_LDR + c + 1] = h1;  Klo[r*ATT_LDR + c + 1] = to_tf32(kv.y - h1);
            Khi[r*ATT_LDR + c + 2] = h2;  Klo[r*ATT_LDR + c + 2] = to_tf32(kv.z - h2);
            Khi[r*ATT_LDR + c + 3] = h3;  Klo[r*ATT_LDR + c + 3] = to_tf32(kv.w - h3);
            float4 vv = *(const float4*)&Vc[((long long)(s0 + r)*NKV_ + kvh)*HD_ + c];
            Vs[r*ATT_LDR + c + 0] = to_tf32(vv.x);
            Vs[r*ATT_LDR + c + 1] = to_tf32(vv.y);
            Vs[r*ATT_LDR + c + 2] = to_tf32(vv.z);
            Vs[r*ATT_LDR + c + 3] = to_tf32(vv.w);
        }
        __syncthreads();

        float s[8][4];
        #pragma unroll
        for (int nt = 0; nt < 8; nt++)
            #pragma unroll
            for (int c = 0; c < 4; c++) s[nt][c] = 0.f;

        #pragma unroll
        for (int kc = 0; kc < 8; kc++) {
            #pragma unroll
            for (int nt = 0; nt < 8; nt++) {
                int srow = nt*8 + grp;
                uint32_t bh0 = __float_as_uint(Khi[srow*ATT_LDR + kc*8 + t4]);
                uint32_t bh1 = __float_as_uint(Khi[srow*ATT_LDR + kc*8 + t4 + 4]);
                uint32_t bl0 = __float_as_uint(Klo[srow*ATT_LDR + kc*8 + t4]);
                uint32_t bl1 = __float_as_uint(Klo[srow*ATT_LDR + kc*8 + t4 + 4]);
                MMA_TF32(s[nt][0], s[nt][1], s[nt][2], s[nt][3],
                         qh[kc][0], qh[kc][1], qh[kc][2], qh[kc][3], bh0, bh1);
                MMA_TF32(s[nt][0], s[nt][1], s[nt][2], s[nt][3],
                         qh[kc][0], qh[kc][1], qh[kc][2], qh[kc][3], bl0, bl1);
                MMA_TF32(s[nt][0], s[nt][1], s[nt][2], s[nt][3],
                         ql[kc][0], ql[kc][1], ql[kc][2], ql[kc][3], bh0, bh1);
            }
        }
        #pragma unroll
        for (int nt = 0; nt < 8; nt++)
            #pragma unroll
            for (int c = 0; c < 4; c++) s[nt][c] *= 0.125f;

        if (s0 == qb) {
            int row0 = wrow + grp, row1 = wrow + grp + 8;
            #pragma unroll
            for (int nt = 0; nt < 8; nt++) {
                int col = nt*8 + 2*t4;
                if (col     > row0) s[nt][0] = -1e30f;
                if (col + 1 > row0) s[nt][1] = -1e30f;
                if (col     > row1) s[nt][2] = -1e30f;
                if (col + 1 > row1) s[nt][3] = -1e30f;
            }
        }

        float rmax0 = -1e30f, rmax1 = -1e30f;
        #pragma unroll
        for (int nt = 0; nt < 8; nt++) {
            rmax0 = fmaxf(rmax0, fmaxf(s[nt][0], s[nt][1]));
            rmax1 = fmaxf(rmax1, fmaxf(s[nt][2], s[nt][3]));
        }
        rmax0 = fmaxf(rmax0, __shfl_xor_sync(0xffffffffu, rmax0, 1));
        rmax0 = fmaxf(rmax0, __shfl_xor_sync(0xffffffffu, rmax0, 2));
        rmax1 = fmaxf(rmax1, __shfl_xor_sync(0xffffffffu, rmax1, 1));
        rmax1 = fmaxf(rmax1, __shfl_xor_sync(0xffffffffu, rmax1, 2));

        float mn0 = fmaxf(m0, rmax0), mn1 = fmaxf(m1, rmax1);
        float corr0 = __expf(m0 - mn0), corr1 = __expf(m1 - mn1);
        l0 *= corr0; l1 *= corr1;
        #pragma unroll
        for (int nt = 0; nt < 8; nt++) {
            o[nt][0] *= corr0; o[nt][1] *= corr0;
            o[nt][2] *= corr1; o[nt][3] *= corr1;
        }
        m0 = mn0; m1 = mn1;

        int prow0 = (wrow + grp) * ATT_LDR, prow1 = (wrow + grp + 8) * ATT_LDR;
        #pragma unroll
        for (int nt = 0; nt < 8; nt++) {
            int col = nt*8 + 2*t4;
            float p0 = __expf(s[nt][0] - mn0);
            float p1 = __expf(s[nt][1] - mn0);
            float p2 = __expf(s[nt][2] - mn1);
            float p3 = __expf(s[nt][3] - mn1);
            l0 += p0 + p1; l1 += p2 + p3;
            *(float2*)&Ps[prow0 + col] = make_float2(p0, p1);
            *(float2*)&Ps[prow1 + col] = make_float2(p2, p3);
        }
        __syncwarp();

        #pragma unroll
        for (int kc = 0; kc < 8; kc++) {
            uint32_t a0 = tf32_bits(Ps[prow0 + kc*8 + t4]);
            uint32_t a1 = tf32_bits(Ps[prow1 + kc*8 + t4]);
            uint32_t a2 = tf32_bits(Ps[prow0 + kc*8 + t4 + 4]);
            uint32_t a3 = tf32_bits(Ps[prow1 + kc*8 + t4 + 4]);
            #pragma unroll
            for (int nt = 0; nt < 8; nt++) {
                uint32_t b0 = __float_as_uint(Vs[(kc*8 + t4    )*ATT_LDR + nt*8 + grp]);
                uint32_t b1 = __float_as_uint(Vs[(kc*8 + t4 + 4)*ATT_LDR + nt*8 + grp]);
                MMA_TF32(o[nt][0], o[nt][1], o[nt][2], o[nt][3],
                         a0, a1, a2, a3, b0, b1);
            }
        }
        __syncthreads();
    }

    l0 += __shfl_xor_sync(0xffffffffu, l0, 1);
    l0 += __shfl_xor_sync(0xffffffffu, l0, 2);
    l1 += __shfl_xor_sync(0xffffffffu, l1, 1);
    l1 += __shfl_xor_sync(0xffffffffu, l1, 2);
    float inv0 = 1.f / l0, inv1 = 1.f / l1;
    int tg0 = qb + wrow + grp, tg1 = tg0 + 8;
    #pragma unroll
    for (int nt = 0; nt < 8; nt++) {
        int col = h*HD_ + nt*8 + 2*t4;
        *(float2*)&O[(long long)tg0*H_ + col] = make_float2(o[nt][0]*inv0, o[nt][1]*inv0);
        *(float2*)&O[(long long)tg1*H_ + col] = make_float2(o[nt][2]*inv1, o[nt][3]*inv1);
    }
}

// ---------------------------------------------------------------------------
// Router: warp per token. Exact replication of group top-k routing (fp32).
// ---------------------------------------------------------------------------
__global__ __launch_bounds__(128) void router_kernel(
    const float* __restrict__ h2, const float* __restrict__ Wg,
    const float* __restrict__ bias, int* __restrict__ ids,
    float* __restrict__ wout)
{
    int warp = threadIdx.x >> 5, lane = threadIdx.x & 31;
    int t = blockIdx.x * 4 + warp;
    const float* h = h2 + (long long)t * H_;
    float acc = 0.f;
    for (int k = 0; k < H_; k++) acc += __ldg(&h[k]) * __ldg(&Wg[k*E_ + lane]);
    float scr = 1.f / (1.f + expf(-acc));
    __shared__ float s_scr[4][E_];
    __shared__ float s_sfc[4][E_];
    s_scr[warp][lane] = scr;
    s_sfc[warp][lane] = scr + bias[lane];
    __syncwarp();
    if (lane == 0) {
        float* sc = s_scr[warp];
        float* sf = s_sfc[warp];
        float gs[NG_];
        for (int g = 0; g < NG_; g++) {
            float m1 = -1e30f, m2 = -1e30f;
            for (int j = 0; j < E_/NG_; j++) {
                float v = sf[g*(E_/NG_) + j];
                if (v > m1) { m2 = m1; m1 = v; }
                else if (v > m2) { m2 = v; }
            }
            gs[g] = m1 + m2;
        }
        int g1 = 0;
        for (int g = 1; g < NG_; g++) if (gs[g] > gs[g1]) g1 = g;
        int g2 = -1;
        for (int g = 0; g < NG_; g++) {
            if (g == g1) continue;
            if (g2 < 0 || gs[g] > gs[g2]) g2 = g;
        }
        bool used[E_];
        for (int e = 0; e < E_; e++) used[e] = false;
        int sel[TOPK_];
        for (int kk = 0; kk < TOPK_; kk++) {
            int best = -1; float bv = -1e30f;
            for (int e = 0; e < E_; e++) {
                int g = e >> 3;
                if ((g != g1 && g != g2) || used[e]) continue;
                if (sf[e] > bv) { bv = sf[e]; best = e; }
            }
            used[best] = true;
            sel[kk] = best;
        }
        float wsum = 0.f, wv[TOPK_];
        for (int kk = 0; kk < TOPK_; kk++) { wv[kk] = sc[sel[kk]]; wsum += wv[kk]; }
        for (int kk = 0; kk < TOPK_; kk++) {
            ids[t*TOPK_ + kk]  = sel[kk];
            wout[t*TOPK_ + kk] = wv[kk] / wsum;
        }
    }
}

// ---------------------------------------------------------------------------
// Counting sort of (token,slot) by expert. Single block.
// ---------------------------------------------------------------------------
__global__ __launch_bounds__(256) void sort_kernel(
    const int* __restrict__ ids, int* __restrict__ sorted_token,
    int* __restrict__ slotpos, int* __restrict__ offs)
{
    __shared__ int cnt[E_], start[E_];
    int tid = threadIdx.x;
    if (tid < E_) cnt[tid] = 0;
    __syncthreads();
    for (int i = tid; i < T_*TOPK_; i += blockDim.x) atomicAdd(&cnt[ids[i]], 1);
    __syncthreads();
    if (tid == 0) {
        int acc = 0;
        for (int e = 0; e < E_; e++) { offs[e] = acc; start[e] = acc; acc += cnt[e]; }
        offs[E_] = acc;
    }
    __syncthreads();
    for (int i = tid; i < T_*TOPK_; i += blockDim.x) {
        int e = ids[i];
        int pos = atomicAdd(&start[e], 1);
        sorted_token[pos] = i >> 2;
        slotpos[i] = pos;
    }
}

// ---------------------------------------------------------------------------
// act = silu(gu[:, :IM]) * gu[:, IM:]
// ---------------------------------------------------------------------------
__global__ __launch_bounds__(256) void silu_mul_kernel(
    const float* __restrict__ gu, float* __restrict__ out, int rows, int im)
{
    long long idx = (long long)blockIdx.x * blockDim.x + threadIdx.x;
    long long total = (long long)rows * im;
    if (idx >= total) return;
    long long r = idx / im;
    int j = (int)(idx - r * im);
    float a = gu[r*(2*im) + j];
    float b = gu[r*(2*im) + im + j];
    float s = a / (1.f + __expf(-a));
    out[idx] = s * b;
}

// ---------------------------------------------------------------------------
// out[t] = shared[t] + sum_k w[t,k] * slot_out[slotpos[t,k]]
// ---------------------------------------------------------------------------
__global__ __launch_bounds__(256) void combine_kernel(
    const float* __restrict__ shexp, const float* __restrict__ slot_out,
    const int* __restrict__ slotpos, const float* __restrict__ w,
    float* __restrict__ out)
{
    int t = blockIdx.x;
    int i = threadIdx.x;
    int p[TOPK_]; float wv[TOPK_];
    #pragma unroll
    for (int k = 0; k < TOPK_; k++) { p[k] = slotpos[t*TOPK_+k]; wv[k] = w[t*TOPK_+k]; }
    float4 acc = ((const float4*)(shexp + (long long)t*H_))[i];
    #pragma unroll
    for (int k = 0; k < TOPK_; k++) {
        float4 v = ((const float4*)(slot_out + (long long)p[k]*H_))[i];
        acc.x += wv[k]*v.x; acc.y += wv[k]*v.y; acc.z += wv[k]*v.z; acc.w += wv[k]*v.w;
    }
    ((float4*)(out + (long long)t*H_))[i] = acc;
}

// ---------------------------------------------------------------------------
// Launch
// ---------------------------------------------------------------------------
extern "C" void kernel_launch(void* const* d_in, const int* in_sizes, int n_in,
                              void* d_out, int out_size)
{
    const float* hidden    = (const float*)d_in[0];
    const float* residual  = (const float*)d_in[1];
    const float* in_ln_w   = (const float*)d_in[2];
    const float* post_ln_w = (const float*)d_in[3];
    const float* q_norm_w  = (const float*)d_in[4];
    const float* k_norm_w  = (const float*)d_in[5];
    const float* Wqkv      = (const float*)d_in[6];
    const float* Wo        = (const float*)d_in[7];
    const float* Wg        = (const float*)d_in[8];
    const float* gate_bias = (const float*)d_in[9];
    const float* Wgu       = (const float*)d_in[10];
    const float* Wd        = (const float*)d_in[11];
    const float* Wgu_sh    = (const float*)d_in[12];
    const float* Wd_sh     = (const float*)d_in[13];
    const int*   positions = (const int*)d_in[14];

    float* out_hidden = (float*)d_out;
    float* out_resid  = out_hidden + (size_t)T_ * H_;

    float *p_r1, *p_ln1, *p_qkv, *p_q, *p_k, *p_v, *p_att, *p_h2;
    float *p_w, *p_gu, *p_act, *p_slot, *p_gus, *p_actsh, *p_shared;
    int *p_ids, *p_sorted, *p_slotpos, *p_offs;
    cudaGetSymbolAddress((void**)&p_r1,      g_r1);
    cudaGetSymbolAddress((void**)&p_ln1,     g_ln1);
    cudaGetSymbolAddress((void**)&p_qkv,     g_qkv);
    cudaGetSymbolAddress((void**)&p_q,       g_q);
    cudaGetSymbolAddress((void**)&p_k,       g_k);
    cudaGetSymbolAddress((void**)&p_v,       g_v);
    cudaGetSymbolAddress((void**)&p_att,     g_att);
    cudaGetSymbolAddress((void**)&p_h2,      g_h2);
    cudaGetSymbolAddress((void**)&p_w,       g_w);
    cudaGetSymbolAddress((void**)&p_ids,     g_ids);
    cudaGetSymbolAddress((void**)&p_sorted,  g_sorted);
    cudaGetSymbolAddress((void**)&p_slotpos, g_slotpos);
    cudaGetSymbolAddress((void**)&p_offs,    g_offs);
    cudaGetSymbolAddress((void**)&p_gu,      g_gu);
    cudaGetSymbolAddress((void**)&p_act,     g_actbuf);
    cudaGetSymbolAddress((void**)&p_slot,    g_slot);
    cudaGetSymbolAddress((void**)&p_gus,     g_gus);
    cudaGetSymbolAddress((void**)&p_actsh,   g_actsh);
    cudaGetSymbolAddress((void**)&p_shared,  g_shared);

    // Idempotent, unconditional (no static guards — harness rule).
    cudaFuncSetAttribute(flash_attn_kernel,
                         cudaFuncAttributeMaxDynamicSharedMemorySize,
                         ATT_SMEM_FLOATS * (int)sizeof(float));

    // 1) r1 = hidden + residual ; ln1 = rms(r1)*in_ln_w
    add_rms_kernel<<<T_, 256>>>(hidden, residual, in_ln_w, p_r1, p_ln1);

    // 2) qkv = ln1 @ Wqkv  (3xTF32 tensor cores, fp32-class accuracy)
    tf32gemm3x_kernel<false><<<dim3(1536/128, T_/128), 256>>>(
        p_ln1, Wqkv, p_qkv, nullptr, T_, 1536, H_);

    // 3) per-head rms + rope
    qknorm_rope_kernel<<<T_, 256>>>(p_qkv, q_norm_w, k_norm_w, positions,
                                    p_q, p_k, p_v);

    // 4) attention (flash, 3xTF32 scores + tf32 PV)
    flash_attn_kernel<<<dim3(T_/64, NH_), 128,
                        ATT_SMEM_FLOATS * sizeof(float)>>>(p_q, p_k, p_v, p_att);

    // 5) r2 = att @ Wo + r1 -> out_resid (3xTF32, fp32-class accuracy)
    tf32gemm3x_kernel<true><<<dim3(H_/128, T_/128), 256>>>(
        p_att, Wo, out_resid, p_r1, T_, H_, H_);

    // 6) h2 = rms(r2)*post_ln_w
    add_rms_kernel<<<T_, 256>>>(out_resid, nullptr, post_ln_w, nullptr, p_h2);

    // 7) router (fp32 exact)
    router_kernel<<<T_/4, 128>>>(p_h2, Wg, gate_bias, p_ids, p_w);

    // 8) counting sort by expert
    sort_kernel<<<1, 256>>>(p_ids, p_sorted, p_slotpos, p_offs);

    // 9) routed up-proj (tf32 TC, gathered+segmented)
    tf32gemm_kernel<true,true><<<dim3(2*IM_/128, 64, E_), 256>>>(
        p_h2, Wgu, p_gu, 0, 2*IM_, H_, p_sorted, p_offs,
        (long long)H_ * 2*IM_);

    // 10) silu-mul for routed
    silu_mul_kernel<<<(T_*TOPK_*IM_ + 255)/256, 256>>>(p_gu, p_act, T_*TOPK_, IM_);

    // 11) routed down-proj (tf32 TC, segmented)
    tf32gemm_kernel<true,false><<<dim3(H_/128, 64, E_), 256>>>(
        p_act, Wd, p_slot, 0, H_, IM_, nullptr, p_offs,
        (long long)IM_ * H_);

    // 12) shared expert up (tf32 TC)
    tf32gemm_kernel<false,false><<<dim3(2*ISH_/128, T_/128), 256>>>(
        p_h2, Wgu_sh, p_gus, T_, 2*ISH_, H_, nullptr, nullptr, 0);

    // 13) silu-mul shared
    silu_mul_kernel<<<(T_*ISH_ + 255)/256, 256>>>(p_gus, p_actsh, T_, ISH_);

    // 14) shared expert down (tf32 TC)
    tf32gemm_kernel<false,false><<<dim3(H_/128, T_/128), 256>>>(
        p_actsh, Wd_sh, p_shared, T_, H_, ISH_, nullptr, nullptr, 0);

    // 15) out_hidden = shared + sum_k w_k * slot_out
    combine_kernel<<<T_, 256>>>(p_shared, p_slot, p_slotpos, p_w, out_hidden);
}

// round 8
// speedup vs baseline: 2.8823x; 1.2858x over previous
#include <cuda_runtime.h>
#include <cuda_bf16.h>
#include <math.h>
#include <stdint.h>

// ---------------------------------------------------------------------------
// Problem constants
// ---------------------------------------------------------------------------
#define T_   2048
#define H_   1024
#define NH_  16
#define NKV_ 4
#define HD_  64
#define E_   32
#define TOPK_ 4
#define NG_  4
#define TG_  2
#define IM_  384
#define ISH_ 384
#define ROT_ 32      // HD/2
#define EPS_ 1e-5f

// ---------------------------------------------------------------------------
// Scratch (device globals — allocation-free per harness rules)
// ---------------------------------------------------------------------------
__device__ float g_r1     [T_*H_];
__device__ float g_ln1    [T_*H_];
__device__ float g_qkv    [T_*1536];
__device__ float g_q      [T_*NH_*HD_];
__device__ float g_k      [T_*NKV_*HD_];
__device__ float g_v      [T_*NKV_*HD_];
__device__ float g_att    [T_*H_];
__device__ float g_h2     [T_*H_];
__device__ float g_w      [T_*TOPK_];
__device__ int   g_ids    [T_*TOPK_];
__device__ int   g_sorted [T_*TOPK_];
__device__ int   g_slotpos[T_*TOPK_];
__device__ int   g_offs   [E_+1];
__device__ float g_gu     [T_*TOPK_*2*IM_];
__device__ float g_actbuf [T_*TOPK_*IM_];
__device__ float g_slot   [T_*TOPK_*H_];
__device__ float g_gus    [T_*2*ISH_];
__device__ float g_actsh  [T_*ISH_];
__device__ float g_shared [T_*H_];

// ---------------------------------------------------------------------------
// Helpers
// ---------------------------------------------------------------------------
__device__ __forceinline__ float to_tf32(float x) {
    uint32_t u;
    asm("cvt.rna.tf32.f32 %0, %1;" : "=r"(u) : "f"(x));
    return __uint_as_float(u);
}
__device__ __forceinline__ uint32_t tf32_bits(float x) {
    uint32_t u;
    asm("cvt.rna.tf32.f32 %0, %1;" : "=r"(u) : "f"(x));
    return u;
}

#define MMA_TF32(d0,d1,d2,d3,a0,a1,a2,a3,b0,b1)                               \
    asm volatile(                                                             \
        "mma.sync.aligned.m16n8k8.row.col.f32.tf32.tf32.f32 "                 \
        "{%0,%1,%2,%3},{%4,%5,%6,%7},{%8,%9},{%0,%1,%2,%3};"                  \
        : "+f"(d0), "+f"(d1), "+f"(d2), "+f"(d3)                              \
        : "r"(a0), "r"(a1), "r"(a2), "r"(a3), "r"(b0), "r"(b1))

// cp.async 16B; src_size 0 => zero-fill destination
#define CP_ASYNC16(dst_u32, src_ptr, src_sz)                                  \
    asm volatile("cp.async.cg.shared.global [%0], [%1], 16, %2;"              \
                 :: "r"(dst_u32), "l"(src_ptr), "r"(src_sz))
#define CP_COMMIT()  asm volatile("cp.async.commit_group;")
#define CP_WAIT1()   asm volatile("cp.async.wait_group 1;")
#define CP_WAIT0()   asm volatile("cp.async.wait_group 0;")

__device__ __forceinline__ uint32_t smem_u32(const void* p) {
    return (uint32_t)__cvta_generic_to_shared(p);
}

// ---------------------------------------------------------------------------
// add + RMSNorm (row per block, 256 threads, float4). b / resid optional.
// ---------------------------------------------------------------------------
__global__ __launch_bounds__(256) void add_rms_kernel(
    const float* __restrict__ a, const float* __restrict__ b,
    const float* __restrict__ w, float* __restrict__ resid,
    float* __restrict__ out)
{
    int t = blockIdx.x;
    int i = threadIdx.x;
    float4 va = ((const float4*)(a + (long long)t*H_))[i];
    if (b) {
        float4 vb = ((const float4*)(b + (long long)t*H_))[i];
        va.x += vb.x; va.y += vb.y; va.z += vb.z; va.w += vb.w;
    }
    if (resid) ((float4*)(resid + (long long)t*H_))[i] = va;
    float ss = va.x*va.x + va.y*va.y + va.z*va.z + va.w*va.w;
    __shared__ float sred[8];
    #pragma unroll
    for (int off = 16; off; off >>= 1) ss += __shfl_xor_sync(0xffffffffu, ss, off);
    if ((i & 31) == 0) sred[i >> 5] = ss;
    __syncthreads();
    if (i < 8) {
        float v = sred[i];
        #pragma unroll
        for (int off = 4; off; off >>= 1) v += __shfl_xor_sync(0xffu, v, off);
        if (i == 0) sred[0] = v;
    }
    __syncthreads();
    float rs = rsqrtf(sred[0] / (float)H_ + EPS_);
    float4 vw = ((const float4*)w)[i];
    va.x *= rs * vw.x; va.y *= rs * vw.y; va.z *= rs * vw.z; va.w *= rs * vw.w;
    ((float4*)(out + (long long)t*H_))[i] = va;
}

// ---------------------------------------------------------------------------
// Pipelined tf32 tensor-core GEMM. 128x128x16 tile, 256 threads, 2-stage
// cp.async double buffering; fp32 tiles in smem, tf32 conversion at
// fragment-load time. THREE_X: 3xTF32 hi/lo (fp32-class accuracy).
//   SEG:    grid.z = expert; rows in [segoffs[z], segoffs[z+1]); B += z*bStride
//   GATHER: A row index from gather[globalRow]
//   ADD:    C = A@B + addsrc
// ---------------------------------------------------------------------------
template<bool THREE_X, bool SEG, bool GATHER, bool ADD>
__global__ __launch_bounds__(256) void tcgemm_kernel(
    const float* __restrict__ A, const float* __restrict__ Bbase,
    float* __restrict__ C, const float* __restrict__ addsrc,
    int M, int N, int K,
    const int* __restrict__ gather, const int* __restrict__ segoffs,
    long long bStride)
{
    constexpr int BK = 16;
    constexpr int ALD = BK + 4;     // 20 floats (80B, 16B-aligned rows)
    constexpr int BLD = 128 + 8;    // 136 floats (544B, 16B-aligned rows)
    __shared__ float As[2][128][ALD];
    __shared__ float Bs[2][BK][BLD];

    int rowBeg, rowEnd, z = 0;
    if (SEG) {
        z = blockIdx.z;
        rowBeg = segoffs[z];
        rowEnd = segoffs[z+1];
    } else {
        rowBeg = 0;
        rowEnd = M;
    }
    int row0 = rowBeg + blockIdx.y * 128;
    if (row0 >= rowEnd) return;
    int col0 = blockIdx.x * 128;
    const float* B = SEG ? (Bbase + (long long)z * bStride) : Bbase;

    int tid = threadIdx.x, lane = tid & 31, warp = tid >> 5;
    int grp = lane >> 2, t4 = lane & 3;
    int wm = (warp >> 2) * 64;
    int wn = (warp & 3) * 32;

    // A loader: rows ar, ar+64, float4 chunk av
    int ar = tid >> 2, av = tid & 3;
    int r0g = row0 + ar, r1g = row0 + ar + 64;
    bool v0 = r0g < rowEnd, v1 = r1g < rowEnd;
    long long sr0 = GATHER ? (v0 ? gather[r0g] : 0) : (v0 ? (long long)r0g : 0);
    long long sr1 = GATHER ? (v1 ? gather[r1g] : 0) : (v1 ? (long long)r1g : 0);
    unsigned sz0 = v0 ? 16u : 0u, sz1 = v1 ? 16u : 0u;
    // B loader: k-row bk, float4 chunks bn, bn+16
    int bk = tid >> 4, bn = tid & 15;

    uint32_t aDst0 = smem_u32(&As[0][ar][av*4]);
    uint32_t aDst1 = smem_u32(&As[0][ar+64][av*4]);
    uint32_t bDst0 = smem_u32(&Bs[0][bk][bn*4]);
    uint32_t bDst1 = smem_u32(&Bs[0][bk][bn*4 + 64]);
    const unsigned aStage = sizeof(float)*128*ALD;
    const unsigned bStage = sizeof(float)*BK*BLD;

    const int nIter = K / BK;

    // prologue: stage 0
    {
        CP_ASYNC16(aDst0, A + sr0*K + av*4, sz0);
        CP_ASYNC16(aDst1, A + sr1*K + av*4, sz1);
        const float* bsrc = B + (long long)bk * N + col0 + bn*4;
        CP_ASYNC16(bDst0, bsrc, 16u);
        CP_ASYNC16(bDst1, bsrc + 64, 16u);
        CP_COMMIT();
    }

    float acc[4][4][4];
    #pragma unroll
    for (int mt = 0; mt < 4; mt++)
        #pragma unroll
        for (int nt = 0; nt < 4; nt++)
            #pragma unroll
            for (int c = 0; c < 4; c++) acc[mt][nt][c] = 0.f;

    for (int it = 0; it < nIter; it++) {
        int buf = it & 1;
        if (it + 1 < nIter) {
            int nb = (it + 1) & 1;
            int k0 = (it + 1) * BK;
            CP_ASYNC16(aDst0 + nb*aStage, A + sr0*K + k0 + av*4, sz0);
            CP_ASYNC16(aDst1 + nb*aStage, A + sr1*K + k0 + av*4, sz1);
            const float* bsrc = B + (long long)(k0 + bk) * N + col0 + bn*4;
            CP_ASYNC16(bDst0 + nb*bStage, bsrc, 16u);
            CP_ASYNC16(bDst1 + nb*bStage, bsrc + 64, 16u);
            CP_COMMIT();
            CP_WAIT1();
        } else {
            CP_WAIT0();
        }
        __syncthreads();

        #pragma unroll
        for (int ks = 0; ks < 2; ks++) {
            // A fragments (convert at load)
            uint32_t ah[4][4], al[4][4];
            #pragma unroll
            for (int mt = 0; mt < 4; mt++) {
                int r = wm + mt*16;
                #pragma unroll
                for (int j = 0; j < 4; j++) {
                    int rr = r + grp + (j & 1) * 8;
                    int cc = ks*8 + t4 + (j >> 1) * 4;
                    float x = As[buf][rr][cc];
                    if (THREE_X) {
                        float hi = to_tf32(x);
                        ah[mt][j] = __float_as_uint(hi);
                        al[mt][j] = tf32_bits(x - hi);
                    } else {
                        ah[mt][j] = tf32_bits(x);
                    }
                }
            }
            uint32_t bh[4][2], bl[4][2];
            #pragma unroll
            for (int nt = 0; nt < 4; nt++) {
                #pragma unroll
                for (int j = 0; j < 2; j++) {
                    float x = Bs[buf][ks*8 + t4 + j*4][wn + nt*8 + grp];
                    if (THREE_X) {
                        float hi = to_tf32(x);
                        bh[nt][j] = __float_as_uint(hi);
                        bl[nt][j] = tf32_bits(x - hi);
                    } else {
                        bh[nt][j] = tf32_bits(x);
                    }
                }
            }
            #pragma unroll
            for (int mt = 0; mt < 4; mt++)
                #pragma unroll
                for (int nt = 0; nt < 4; nt++) {
                    MMA_TF32(acc[mt][nt][0], acc[mt][nt][1],
                             acc[mt][nt][2], acc[mt][nt][3],
                             ah[mt][0], ah[mt][1], ah[mt][2], ah[mt][3],
                             bh[nt][0], bh[nt][1]);
                    if (THREE_X) {
                        MMA_TF32(acc[mt][nt][0], acc[mt][nt][1],
                                 acc[mt][nt][2], acc[mt][nt][3],
                                 ah[mt][0], ah[mt][1], ah[mt][2], ah[mt][3],
                                 bl[nt][0], bl[nt][1]);
                        MMA_TF32(acc[mt][nt][0], acc[mt][nt][1],
                                 acc[mt][nt][2], acc[mt][nt][3],
                                 al[mt][0], al[mt][1], al[mt][2], al[mt][3],
                                 bh[nt][0], bh[nt][1]);
                    }
                }
        }
        __syncthreads();   // compute done before this buffer is refilled (it+2)
    }

    #pragma unroll
    for (int mt = 0; mt < 4; mt++) {
        int r0 = row0 + wm + mt*16 + grp;
        int r1 = r0 + 8;
        #pragma unroll
        for (int nt = 0; nt < 4; nt++) {
            int col = col0 + wn + nt*8 + 2*t4;
            if (r0 < rowEnd) {
                float2 v = make_float2(acc[mt][nt][0], acc[mt][nt][1]);
                if (ADD) {
                    float2 a2 = *reinterpret_cast<const float2*>(
                        addsrc + (long long)r0*N + col);
                    v.x += a2.x; v.y += a2.y;
                }
                *reinterpret_cast<float2*>(C + (long long)r0*N + col) = v;
            }
            if (r1 < rowEnd) {
                float2 v = make_float2(acc[mt][nt][2], acc[mt][nt][3]);
                if (ADD) {
                    float2 a2 = *reinterpret_cast<const float2*>(
                        addsrc + (long long)r1*N + col);
                    v.x += a2.x; v.y += a2.y;
                }
                *reinterpret_cast<float2*>(C + (long long)r1*N + col) = v;
            }
        }
    }
}

// ---------------------------------------------------------------------------
// Per-head RMSNorm + RoPE for q and k; copy v. Block = 1 token, 256 threads.
// ---------------------------------------------------------------------------
__global__ __launch_bounds__(256) void qknorm_rope_kernel(
    const float* __restrict__ qkv,
    const float* __restrict__ qw, const float* __restrict__ kw,
    const int* __restrict__ positions,
    float* __restrict__ Qo, float* __restrict__ Ko, float* __restrict__ Vo)
{
    int t = blockIdx.x;
    int warp = threadIdx.x >> 5, lane = threadIdx.x & 31;
    float p = (float)positions[t];

    for (int vec = warp; vec < NH_ + NKV_; vec += 8) {
        bool isq = vec < NH_;
        const float* src = qkv + (long long)t*1536 + vec*HD_;
        float x0 = src[lane], x1 = src[lane + 32];
        float ss = x0*x0 + x1*x1;
        #pragma unroll
        for (int off = 16; off; off >>= 1) ss += __shfl_xor_sync(0xffffffffu, ss, off);
        float r = rsqrtf(ss / (float)HD_ + EPS_);
        const float* w = isq ? qw : kw;
        x0 = x0 * r * w[lane];
        x1 = x1 * r * w[lane + 32];
        int i = lane & 15;
        float inv = powf(10000.f, -((float)(2*i) / (float)ROT_));
        float ang = p * inv;
        float c = cosf(ang), s = sinf(ang);
        float partner = __shfl_xor_sync(0xffffffffu, x0, 16);
        float y0;
        if (lane < 16) y0 = x0 * c - partner * s;
        else           y0 = partner * s + x0 * c;
        x0 = y0;
        float* dst = isq ? (Qo + ((long long)t*NH_ + vec)*HD_)
                         : (Ko + ((long long)t*NKV_ + (vec - NH_))*HD_);
        dst[lane] = x0;
        dst[lane + 32] = x1;
    }
    for (int i = threadIdx.x; i < NKV_*HD_; i += blockDim.x)
        Vo[(long long)t*NKV_*HD_ + i] = qkv[(long long)t*1536 + 1280 + i];
}

// ---------------------------------------------------------------------------
// Flash attention (tensor cores). Br=64 queries/block, Bc=64 keys/tile.
// 4 warps. S = Q K^T in 3xTF32; P V in plain tf32. O fp32 accumulators.
// ---------------------------------------------------------------------------
#define ATT_LDR 68
#define ATT_SMEM_FLOATS (4*64*ATT_LDR)

__global__ __launch_bounds__(128) void flash_attn_kernel(
    const float* __restrict__ Q, const float* __restrict__ Kc,
    const float* __restrict__ Vc, float* __restrict__ O)
{
    extern __shared__ float sm[];
    float* Ps  = sm;                    // Q staging, then P tile
    float* Khi = sm + 64*ATT_LDR;
    float* Klo = sm + 2*64*ATT_LDR;
    float* Vs  = sm + 3*64*ATT_LDR;

    const int h = blockIdx.y;
    const int kvh = h >> 2;
    const int qb = ((int)gridDim.x - 1 - (int)blockIdx.x) * 64;  // reversed

    int tid = threadIdx.x, lane = tid & 31, warp = tid >> 5;
    int grp = lane >> 2, t4 = lane & 3;
    int wrow = warp * 16;

    for (int idx = tid; idx < 64*16; idx += 128) {
        int r = idx >> 4, c = (idx & 15) * 4;
        float4 v = *(const float4*)&Q[((long long)(qb + r)*NH_ + h)*HD_ + c];
        Ps[r*ATT_LDR + c + 0] = v.x;
        Ps[r*ATT_LDR + c + 1] = v.y;
        Ps[r*ATT_LDR + c + 2] = v.z;
        Ps[r*ATT_LDR + c + 3] = v.w;
    }
    __syncthreads();

    uint32_t qh[8][4], ql[8][4];
    #pragma unroll
    for (int kc = 0; kc < 8; kc++) {
        int r0 = wrow + grp, r1 = wrow + grp + 8;
        int c0 = kc*8 + t4, c1 = c0 + 4;
        float x, hi;
        x = Ps[r0*ATT_LDR + c0]; hi = to_tf32(x);
        qh[kc][0] = __float_as_uint(hi); ql[kc][0] = tf32_bits(x - hi);
        x = Ps[r1*ATT_LDR + c0]; hi = to_tf32(x);
        qh[kc][1] = __float_as_uint(hi); ql[kc][1] = tf32_bits(x - hi);
        x = Ps[r0*ATT_LDR + c1]; hi = to_tf32(x);
        qh[kc][2] = __float_as_uint(hi); ql[kc][2] = tf32_bits(x - hi);
        x = Ps[r1*ATT_LDR + c1]; hi = to_tf32(x);
        qh[kc][3] = __float_as_uint(hi); ql[kc][3] = tf32_bits(x - hi);
    }

    float o[8][4];
    #pragma unroll
    for (int nt = 0; nt < 8; nt++)
        #pragma unroll
        for (int c = 0; c < 4; c++) o[nt][c] = 0.f;
    float m0 = -1e30f, m1 = -1e30f, l0 = 0.f, l1 = 0.f;

    const int nTiles = qb/64 + 1;
    for (int jt = 0; jt < nTiles; jt++) {
        int s0 = jt * 64;
        for (int idx = tid; idx < 64*16; idx += 128) {
            int r = idx >> 4, c = (idx & 15) * 4;
            float4 kv = *(const float4*)&Kc[((long long)(s0 + r)*NKV_ + kvh)*HD_ + c];
            float h0 = to_tf32(kv.x), h1 = to_tf32(kv.y),
                  h2 = to_tf32(kv.z), h3 = to_tf32(kv.w);
            Khi[r*ATT_LDR + c + 0] = h0;  Klo[r*ATT_LDR + c + 0] = to_tf32(kv.x - h0);
            Khi[r*ATT_LDR + c + 1] = h1;  Klo[r*ATT_LDR + c + 1] = to_tf32(kv.y - h1);
            Khi[r*ATT_LDR + c + 2] = h2;  Klo[r*ATT_LDR + c + 2] = to_tf32(kv.z - h2);
            Khi[r*ATT_LDR + c + 3] = h3;  Klo[r*ATT_LDR + c + 3] = to_tf32(kv.w - h3);
            float4 vv = *(const float4*)&Vc[((long long)(s0 + r)*NKV_ + kvh)*HD_ + c];
            Vs[r*ATT_LDR + c + 0] = to_tf32(vv.x);
            Vs[r*ATT_LDR + c + 1] = to_tf32(vv.y);
            Vs[r*ATT_LDR + c + 2] = to_tf32(vv.z);
            Vs[r*ATT_LDR + c + 3] = to_tf32(vv.w);
        }
        __syncthreads();

        float s[8][4];
        #pragma unroll
        for (int nt = 0; nt < 8; nt++)
            #pragma unroll
            for (int c = 0; c < 4; c++) s[nt][c] = 0.f;

        #pragma unroll
        for (int kc = 0; kc < 8; kc++) {
            #pragma unroll
            for (int nt = 0; nt < 8; nt++) {
                int srow = nt*8 + grp;
                uint32_t bh0 = __float_as_uint(Khi[srow*ATT_LDR + kc*8 + t4]);
                uint32_t bh1 = __float_as_uint(Khi[srow*ATT_LDR + kc*8 + t4 + 4]);
                uint32_t bl0 = __float_as_uint(Klo[srow*ATT_LDR + kc*8 + t4]);
                uint32_t bl1 = __float_as_uint(Klo[srow*ATT_LDR + kc*8 + t4 + 4]);
                MMA_TF32(s[nt][0], s[nt][1], s[nt][2], s[nt][3],
                         qh[kc][0], qh[kc][1], qh[kc][2], qh[kc][3], bh0, bh1);
                MMA_TF32(s[nt][0], s[nt][1], s[nt][2], s[nt][3],
                         qh[kc][0], qh[kc][1], qh[kc][2], qh[kc][3], bl0, bl1);
                MMA_TF32(s[nt][0], s[nt][1], s[nt][2], s[nt][3],
                         ql[kc][0], ql[kc][1], ql[kc][2], ql[kc][3], bh0, bh1);
            }
        }
        #pragma unroll
        for (int nt = 0; nt < 8; nt++)
            #pragma unroll
            for (int c = 0; c < 4; c++) s[nt][c] *= 0.125f;

        if (s0 == qb) {
            int row0 = wrow + grp, row1 = wrow + grp + 8;
            #pragma unroll
            for (int nt = 0; nt < 8; nt++) {
                int col = nt*8 + 2*t4;
                if (col     > row0) s[nt][0] = -1e30f;
                if (col + 1 > row0) s[nt][1] = -1e30f;
                if (col     > row1) s[nt][2] = -1e30f;
                if (col + 1 > row1) s[nt][3] = -1e30f;
            }
        }

        float rmax0 = -1e30f, rmax1 = -1e30f;
        #pragma unroll
        for (int nt = 0; nt < 8; nt++) {
            rmax0 = fmaxf(rmax0, fmaxf(s[nt][0], s[nt][1]));
            rmax1 = fmaxf(rmax1, fmaxf(s[nt][2], s[nt][3]));
        }
        rmax0 = fmaxf(rmax0, __shfl_xor_sync(0xffffffffu, rmax0, 1));
        rmax0 = fmaxf(rmax0, __shfl_xor_sync(0xffffffffu, rmax0, 2));
        rmax1 = fmaxf(rmax1, __shfl_xor_sync(0xffffffffu, rmax1, 1));
        rmax1 = fmaxf(rmax1, __shfl_xor_sync(0xffffffffu, rmax1, 2));

        float mn0 = fmaxf(m0, rmax0), mn1 = fmaxf(m1, rmax1);
        float corr0 = __expf(m0 - mn0), corr1 = __expf(m1 - mn1);
        l0 *= corr0; l1 *= corr1;
        #pragma unroll
        for (int nt = 0; nt < 8; nt++) {
            o[nt][0] *= corr0; o[nt][1] *= corr0;
            o[nt][2] *= corr1; o[nt][3] *= corr1;
        }
        m0 = mn0; m1 = mn1;

        int prow0 = (wrow + grp) * ATT_LDR, prow1 = (wrow + grp + 8) * ATT_LDR;
        #pragma unroll
        for (int nt = 0; nt < 8; nt++) {
            int col = nt*8 + 2*t4;
            float p0 = __expf(s[nt][0] - mn0);
            float p1 = __expf(s[nt][1] - mn0);
            float p2 = __expf(s[nt][2] - mn1);
            float p3 = __expf(s[nt][3] - mn1);
            l0 += p0 + p1; l1 += p2 + p3;
            *(float2*)&Ps[prow0 + col] = make_float2(p0, p1);
            *(float2*)&Ps[prow1 + col] = make_float2(p2, p3);
        }
        __syncwarp();

        #pragma unroll
        for (int kc = 0; kc < 8; kc++) {
            uint32_t a0 = tf32_bits(Ps[prow0 + kc*8 + t4]);
            uint32_t a1 = tf32_bits(Ps[prow1 + kc*8 + t4]);
            uint32_t a2 = tf32_bits(Ps[prow0 + kc*8 + t4 + 4]);
            uint32_t a3 = tf32_bits(Ps[prow1 + kc*8 + t4 + 4]);
            #pragma unroll
            for (int nt = 0; nt < 8; nt++) {
                uint32_t b0 = __float_as_uint(Vs[(kc*8 + t4    )*ATT_LDR + nt*8 + grp]);
                uint32_t b1 = __float_as_uint(Vs[(kc*8 + t4 + 4)*ATT_LDR + nt*8 + grp]);
                MMA_TF32(o[nt][0], o[nt][1], o[nt][2], o[nt][3],
                         a0, a1, a2, a3, b0, b1);
            }
        }
        __syncthreads();
    }

    l0 += __shfl_xor_sync(0xffffffffu, l0, 1);
    l0 += __shfl_xor_sync(0xffffffffu, l0, 2);
    l1 += __shfl_xor_sync(0xffffffffu, l1, 1);
    l1 += __shfl_xor_sync(0xffffffffu, l1, 2);
    float inv0 = 1.f / l0, inv1 = 1.f / l1;
    int tg0 = qb + wrow + grp, tg1 = tg0 + 8;
    #pragma unroll
    for (int nt = 0; nt < 8; nt++) {
        int col = h*HD_ + nt*8 + 2*t4;
        *(float2*)&O[(long long)tg0*H_ + col] = make_float2(o[nt][0]*inv0, o[nt][1]*inv0);
        *(float2*)&O[(long long)tg1*H_ + col] = make_float2(o[nt][2]*inv1, o[nt][3]*inv1);
    }
}

// ---------------------------------------------------------------------------
// Router: warp per token. Exact replication of group top-k routing (fp32).
// ---------------------------------------------------------------------------
__global__ __launch_bounds__(128) void router_kernel(
    const float* __restrict__ h2, const float* __restrict__ Wg,
    const float* __restrict__ bias, int* __restrict__ ids,
    float* __restrict__ wout)
{
    int warp = threadIdx.x >> 5, lane = threadIdx.x & 31;
    int t = blockIdx.x * 4 + warp;
    const float* h = h2 + (long long)t * H_;
    float acc = 0.f;
    for (int k = 0; k < H_; k++) acc += __ldg(&h[k]) * __ldg(&Wg[k*E_ + lane]);
    float scr = 1.f / (1.f + expf(-acc));
    __shared__ float s_scr[4][E_];
    __shared__ float s_sfc[4][E_];
    s_scr[warp][lane] = scr;
    s_sfc[warp][lane] = scr + bias[lane];
    __syncwarp();
    if (lane == 0) {
        float* sc = s_scr[warp];
        float* sf = s_sfc[warp];
        float gs[NG_];
        for (int g = 0; g < NG_; g++) {
            float m1 = -1e30f, m2 = -1e30f;
            for (int j = 0; j < E_/NG_; j++) {
                float v = sf[g*(E_/NG_) + j];
                if (v > m1) { m2 = m1; m1 = v; }
                else if (v > m2) { m2 = v; }
            }
            gs[g] = m1 + m2;
        }
        int g1 = 0;
        for (int g = 1; g < NG_; g++) if (gs[g] > gs[g1]) g1 = g;
        int g2 = -1;
        for (int g = 0; g < NG_; g++) {
            if (g == g1) continue;
            if (g2 < 0 || gs[g] > gs[g2]) g2 = g;
        }
        bool used[E_];
        for (int e = 0; e < E_; e++) used[e] = false;
        int sel[TOPK_];
        for (int kk = 0; kk < TOPK_; kk++) {
            int best = -1; float bv = -1e30f;
            for (int e = 0; e < E_; e++) {
                int g = e >> 3;
                if ((g != g1 && g != g2) || used[e]) continue;
                if (sf[e] > bv) { bv = sf[e]; best = e; }
            }
            used[best] = true;
            sel[kk] = best;
        }
        float wsum = 0.f, wv[TOPK_];
        for (int kk = 0; kk < TOPK_; kk++) { wv[kk] = sc[sel[kk]]; wsum += wv[kk]; }
        for (int kk = 0; kk < TOPK_; kk++) {
            ids[t*TOPK_ + kk]  = sel[kk];
            wout[t*TOPK_ + kk] = wv[kk] / wsum;
        }
    }
}

// ---------------------------------------------------------------------------
// Counting sort of (token,slot) by expert. Single block.
// ---------------------------------------------------------------------------
__global__ __launch_bounds__(256) void sort_kernel(
    const int* __restrict__ ids, int* __restrict__ sorted_token,
    int* __restrict__ slotpos, int* __restrict__ offs)
{
    __shared__ int cnt[E_], start[E_];
    int tid = threadIdx.x;
    if (tid < E_) cnt[tid] = 0;
    __syncthreads();
    for (int i = tid; i < T_*TOPK_; i += blockDim.x) atomicAdd(&cnt[ids[i]], 1);
    __syncthreads();
    if (tid == 0) {
        int acc = 0;
        for (int e = 0; e < E_; e++) { offs[e] = acc; start[e] = acc; acc += cnt[e]; }
        offs[E_] = acc;
    }
    __syncthreads();
    for (int i = tid; i < T_*TOPK_; i += blockDim.x) {
        int e = ids[i];
        int pos = atomicAdd(&start[e], 1);
        sorted_token[pos] = i >> 2;
        slotpos[i] = pos;
    }
}

// ---------------------------------------------------------------------------
// act = silu(gu[:, :IM]) * gu[:, IM:]
// ---------------------------------------------------------------------------
__global__ __launch_bounds__(256) void silu_mul_kernel(
    const float* __restrict__ gu, float* __restrict__ out, int rows, int im)
{
    long long idx = (long long)blockIdx.x * blockDim.x + threadIdx.x;
    long long total = (long long)rows * im;
    if (idx >= total) return;
    long long r = idx / im;
    int j = (int)(idx - r * im);
    float a = gu[r*(2*im) + j];
    float b = gu[r*(2*im) + im + j];
    float s = a / (1.f + __expf(-a));
    out[idx] = s * b;
}

// ---------------------------------------------------------------------------
// out[t] = shared[t] + sum_k w[t,k] * slot_out[slotpos[t,k]]
// ---------------------------------------------------------------------------
__global__ __launch_bounds__(256) void combine_kernel(
    const float* __restrict__ shexp, const float* __restrict__ slot_out,
    const int* __restrict__ slotpos, const float* __restrict__ w,
    float* __restrict__ out)
{
    int t = blockIdx.x;
    int i = threadIdx.x;
    int p[TOPK_]; float wv[TOPK_];
    #pragma unroll
    for (int k = 0; k < TOPK_; k++) { p[k] = slotpos[t*TOPK_+k]; wv[k] = w[t*TOPK_+k]; }
    float4 acc = ((const float4*)(shexp + (long long)t*H_))[i];
    #pragma unroll
    for (int k = 0; k < TOPK_; k++) {
        float4 v = ((const float4*)(slot_out + (long long)p[k]*H_))[i];
        acc.x += wv[k]*v.x; acc.y += wv[k]*v.y; acc.z += wv[k]*v.z; acc.w += wv[k]*v.w;
    }
    ((float4*)(out + (long long)t*H_))[i] = acc;
}

// ---------------------------------------------------------------------------
// Launch
// ---------------------------------------------------------------------------
extern "C" void kernel_launch(void* const* d_in, const int* in_sizes, int n_in,
                              void* d_out, int out_size)
{
    const float* hidden    = (const float*)d_in[0];
    const float* residual  = (const float*)d_in[1];
    const float* in_ln_w   = (const float*)d_in[2];
    const float* post_ln_w = (const float*)d_in[3];
    const float* q_norm_w  = (const float*)d_in[4];
    const float* k_norm_w  = (const float*)d_in[5];
    const float* Wqkv      = (const float*)d_in[6];
    const float* Wo        = (const float*)d_in[7];
    const float* Wg        = (const float*)d_in[8];
    const float* gate_bias = (const float*)d_in[9];
    const float* Wgu       = (const float*)d_in[10];
    const float* Wd        = (const float*)d_in[11];
    const float* Wgu_sh    = (const float*)d_in[12];
    const float* Wd_sh     = (const float*)d_in[13];
    const int*   positions = (const int*)d_in[14];

    float* out_hidden = (float*)d_out;
    float* out_resid  = out_hidden + (size_t)T_ * H_;

    float *p_r1, *p_ln1, *p_qkv, *p_q, *p_k, *p_v, *p_att, *p_h2;
    float *p_w, *p_gu, *p_act, *p_slot, *p_gus, *p_actsh, *p_shared;
    int *p_ids, *p_sorted, *p_slotpos, *p_offs;
    cudaGetSymbolAddress((void**)&p_r1,      g_r1);
    cudaGetSymbolAddress((void**)&p_ln1,     g_ln1);
    cudaGetSymbolAddress((void**)&p_qkv,     g_qkv);
    cudaGetSymbolAddress((void**)&p_q,       g_q);
    cudaGetSymbolAddress((void**)&p_k,       g_k);
    cudaGetSymbolAddress((void**)&p_v,       g_v);
    cudaGetSymbolAddress((void**)&p_att,     g_att);
    cudaGetSymbolAddress((void**)&p_h2,      g_h2);
    cudaGetSymbolAddress((void**)&p_w,       g_w);
    cudaGetSymbolAddress((void**)&p_ids,     g_ids);
    cudaGetSymbolAddress((void**)&p_sorted,  g_sorted);
    cudaGetSymbolAddress((void**)&p_slotpos, g_slotpos);
    cudaGetSymbolAddress((void**)&p_offs,    g_offs);
    cudaGetSymbolAddress((void**)&p_gu,      g_gu);
    cudaGetSymbolAddress((void**)&p_act,     g_actbuf);
    cudaGetSymbolAddress((void**)&p_slot,    g_slot);
    cudaGetSymbolAddress((void**)&p_gus,     g_gus);
    cudaGetSymbolAddress((void**)&p_actsh,   g_actsh);
    cudaGetSymbolAddress((void**)&p_shared,  g_shared);

    // Idempotent, unconditional (no static guards — harness rule).
    cudaFuncSetAttribute(flash_attn_kernel,
                         cudaFuncAttributeMaxDynamicSharedMemorySize,
                         ATT_SMEM_FLOATS * (int)sizeof(float));

    // 1) r1 = hidden + residual ; ln1 = rms(r1)*in_ln_w
    add_rms_kernel<<<T_, 256>>>(hidden, residual, in_ln_w, p_r1, p_ln1);

    // 2) qkv = ln1 @ Wqkv  (3xTF32 pipelined, fp32-class accuracy)
    tcgemm_kernel<true,false,false,false><<<dim3(1536/128, T_/128), 256>>>(
        p_ln1, Wqkv, p_qkv, nullptr, T_, 1536, H_, nullptr, nullptr, 0);

    // 3) per-head rms + rope
    qknorm_rope_kernel<<<T_, 256>>>(p_qkv, q_norm_w, k_norm_w, positions,
                                    p_q, p_k, p_v);

    // 4) attention (flash, 3xTF32 scores + tf32 PV)
    flash_attn_kernel<<<dim3(T_/64, NH_), 128,
                        ATT_SMEM_FLOATS * sizeof(float)>>>(p_q, p_k, p_v, p_att);

    // 5) r2 = att @ Wo + r1 -> out_resid (3xTF32 pipelined)
    tcgemm_kernel<true,false,false,true><<<dim3(H_/128, T_/128), 256>>>(
        p_att, Wo, out_resid, p_r1, T_, H_, H_, nullptr, nullptr, 0);

    // 6) h2 = rms(r2)*post_ln_w
    add_rms_kernel<<<T_, 256>>>(out_resid, nullptr, post_ln_w, nullptr, p_h2);

    // 7) router (fp32 exact)
    router_kernel<<<T_/4, 128>>>(p_h2, Wg, gate_bias, p_ids, p_w);

    // 8) counting sort by expert
    sort_kernel<<<1, 256>>>(p_ids, p_sorted, p_slotpos, p_offs);

    // 9) routed up-proj (tf32 pipelined, gathered+segmented)
    tcgemm_kernel<false,true,true,false><<<dim3(2*IM_/128, 64, E_), 256>>>(
        p_h2, Wgu, p_gu, nullptr, 0, 2*IM_, H_, p_sorted, p_offs,
        (long long)H_ * 2*IM_);

    // 10) silu-mul for routed
    silu_mul_kernel<<<(T_*TOPK_*IM_ + 255)/256, 256>>>(p_gu, p_act, T_*TOPK_, IM_);

    // 11) routed down-proj (tf32 pipelined, segmented)
    tcgemm_kernel<false,true,false,false><<<dim3(H_/128, 64, E_), 256>>>(
        p_act, Wd, p_slot, nullptr, 0, H_, IM_, nullptr, p_offs,
        (long long)IM_ * H_);

    // 12) shared expert up (tf32 pipelined)
    tcgemm_kernel<false,false,false,false><<<dim3(2*ISH_/128, T_/128), 256>>>(
        p_h2, Wgu_sh, p_gus, nullptr, T_, 2*ISH_, H_, nullptr, nullptr, 0);

    // 13) silu-mul shared
    silu_mul_kernel<<<(T_*ISH_ + 255)/256, 256>>>(p_gus, p_actsh, T_, ISH_);

    // 14) shared expert down (tf32 pipelined)
    tcgemm_kernel<false,false,false,false><<<dim3(H_/128, T_/128), 256>>>(
        p_actsh, Wd_sh, p_shared, nullptr, T_, H_, ISH_, nullptr, nullptr, 0);

    // 15) out_hidden = shared + sum_k w_k * slot_out
    combine_kernel<<<T_, 256>>>(p_shared, p_slot, p_slotpos, p_w, out_hidden);
}